// round 9
// baseline (speedup 1.0000x reference)
#include <cuda_runtime.h>
#include <cuda_fp16.h>
#include <cstdint>

#define N_NODES 50000
#define N_EDGES 800000
#define N_GRAPHS 256
#define IN_CH 128
#define HID 256
#define NB 49   // scan blocks of 1024

// ---------------- scratch (device globals; no allocation allowed) -------------
__device__ int   g_ideg[N_NODES];
__device__ int   g_off[N_NODES + 1];
__device__ int   g_cursor[N_NODES];
__device__ unsigned long long g_state[NB];       // decoupled-lookback state
__device__ __align__(16) int2 g_edge[N_EDGES];   // {src, w-as-int}
__device__ float g_dis[N_NODES];
__device__ __align__(16) __half g_xh[(size_t)N_NODES * IN_CH];
__device__ __align__(16) __half g_xagg[(size_t)N_NODES * IN_CH];
__device__ __align__(16) __half g_Wt[(IN_CH + HID + HID) * HID];
__device__ __align__(16) __half g_xw[(size_t)N_NODES * HID];
__device__ __align__(16) __half g_hA[(size_t)N_NODES * HID];
__device__ __align__(16) __half g_hB[(size_t)N_NODES * HID];
__device__ float g_pooled[N_GRAPHS * HID];
__device__ float g_counts[N_GRAPHS];

// ---------------- helpers ----------------------------------------------------
__device__ __forceinline__ void red_add_v4(float* addr, float4 v) {
    asm volatile("red.global.add.v4.f32 [%0], {%1,%2,%3,%4};"
                 :: "l"(addr), "f"(v.x), "f"(v.y), "f"(v.z), "f"(v.w)
                 : "memory");
}

__device__ __forceinline__ uint4 ldg4(const __half* p) {
    uint4 v;
    asm volatile("ld.global.nc.v4.u32 {%0,%1,%2,%3}, [%4];"
                 : "=r"(v.x), "=r"(v.y), "=r"(v.z), "=r"(v.w) : "l"(p));
    return v;
}
__device__ __forceinline__ uint2 ldg2(const __half* p) {
    uint2 v;
    asm volatile("ld.global.nc.v2.u32 {%0,%1}, [%2];"
                 : "=r"(v.x), "=r"(v.y) : "l"(p));
    return v;
}

__device__ __forceinline__ void h8f(uint4 v, float* f) {
    float2 p0 = __half22float2(*(const __half2*)&v.x);
    float2 p1 = __half22float2(*(const __half2*)&v.y);
    float2 p2 = __half22float2(*(const __half2*)&v.z);
    float2 p3 = __half22float2(*(const __half2*)&v.w);
    f[0] = p0.x; f[1] = p0.y; f[2] = p1.x; f[3] = p1.y;
    f[4] = p2.x; f[5] = p2.y; f[6] = p3.x; f[7] = p3.y;
}

typedef unsigned long long u64t;
__device__ __forceinline__ u64t packf2(float x, float y) {
    u64t u; asm("mov.b64 %0, {%1,%2};" : "=l"(u) : "f"(x), "f"(y)); return u;
}
__device__ __forceinline__ float2 unpackf2(u64t u) {
    float2 f; asm("mov.b64 {%0,%1}, %2;" : "=f"(f.x), "=f"(f.y) : "l"(u)); return f;
}
#define FMA_F32X2(d, a, b, c) \
    asm("fma.rn.f32x2 %0, %1, %2, %3;" : "=l"(d) : "l"(a), "l"(b), "l"(c))

__device__ __forceinline__ void cp16(uint32_t saddr, const void* g, int pbytes) {
    asm volatile("cp.async.ca.shared.global [%0], [%1], 16, %2;"
                 :: "r"(saddr), "l"(g), "r"(pbytes));
}

// ---------------- front kernel: degree/batch counts + fp16 prep, fused -------
#define XF4   (N_NODES * IN_CH / 4)
#define W1E   (IN_CH * HID)
#define W23E  (HID * HID)
#define PREP_ITEMS (XF4 + W1E + 2 * W23E)
__global__ void k_front(const int* __restrict__ col, int* __restrict__ ideg,
                        const int* __restrict__ batch, float* __restrict__ counts,
                        const float* __restrict__ x, __half* __restrict__ xh,
                        const float* __restrict__ W1, const float* __restrict__ W2,
                        const float* __restrict__ W3, __half* __restrict__ Wt) {
    int i = blockIdx.x * blockDim.x + threadIdx.x;
    if (i < N_EDGES) atomicAdd(&ideg[col[i]], 1);
    if (i < N_NODES) atomicAdd(&counts[batch[i]], 1.0f);
    int p = i;
    if (p < XF4) {
        float4 v = ((const float4*)x)[p];
        ((__half2*)xh)[p * 2]     = __floats2half2_rn(v.x, v.y);
        ((__half2*)xh)[p * 2 + 1] = __floats2half2_rn(v.z, v.w);
    } else {
        p -= XF4;
        if (p < W1E) {
            int k = p >> 8, n = p & 255;
            Wt[(size_t)n * IN_CH + k] = __float2half(W1[p]);
        } else {
            p -= W1E;
            if (p < W23E) {
                int k = p >> 8, n = p & 255;
                Wt[W1E + (size_t)n * HID + k] = __float2half(W2[p]);
            } else {
                p -= W23E;
                if (p < W23E) {
                    int k = p >> 8, n = p & 255;
                    Wt[W1E + W23E + (size_t)n * HID + k] = __float2half(W3[p]);
                }
            }
        }
    }
}

// ---------------- CSR build ---------------------------------------------------
__global__ void k_zero(int* ideg, float* pooled, float* counts,
                       unsigned long long* state) {
    int i = blockIdx.x * blockDim.x + threadIdx.x;
    if (i < N_NODES) ideg[i] = 0;
    if (i < N_GRAPHS * HID) pooled[i] = 0.0f;
    if (i < N_GRAPHS) counts[i] = 0.0f;
    if (i < NB) state[i] = 0ULL;
}

// single-kernel exclusive scan with warp-parallel decoupled lookback.
__global__ __launch_bounds__(1024) void k_scan_fused(const int* __restrict__ ideg,
                                                     int* __restrict__ off,
                                                     int* __restrict__ cursor,
                                                     float* __restrict__ dis,
                                                     unsigned long long* __restrict__ state) {
    __shared__ int warpsum[32];
    __shared__ int s_base;
    const int b = blockIdx.x, t = threadIdx.x;
    const int lane = t & 31, w = t >> 5;
    int i = b * 1024 + t;
    int v = (i < N_NODES) ? ideg[i] : 0;
    int inc = v;
#pragma unroll
    for (int s = 1; s < 32; s <<= 1) {
        int u = __shfl_up_sync(0xffffffffu, inc, s);
        if (lane >= s) inc += u;
    }
    if (lane == 31) warpsum[w] = inc;
    __syncthreads();
    if (w == 0) {
        int wi = warpsum[lane];
#pragma unroll
        for (int s = 1; s < 32; s <<= 1) {
            int u = __shfl_up_sync(0xffffffffu, wi, s);
            if (lane >= s) wi += u;
        }
        warpsum[lane] = wi;
        unsigned total = (unsigned)__shfl_sync(0xffffffffu, wi, 31);
        if (b == 0) {
            if (lane == 0) {
                atomicExch(&state[0], (2ULL << 32) | total);
                s_base = 0;
            }
        } else {
            if (lane == 0) atomicExch(&state[b], (1ULL << 32) | total);
            unsigned running = 0;
            int idx = b - 1;
            while (true) {
                int ii = idx - lane;
                unsigned long long s64 = (ii >= 0)
                    ? atomicAdd(&state[ii], 0ULL) : (2ULL << 32);
                unsigned flag = (unsigned)(s64 >> 32);
                if (__all_sync(0xffffffffu, flag != 0)) {
                    unsigned pm = __ballot_sync(0xffffffffu, flag == 2u);
                    if (pm) {
                        int k = __ffs(pm) - 1;
                        unsigned c = (lane <= k) ? (unsigned)s64 : 0u;
#pragma unroll
                        for (int o = 16; o; o >>= 1)
                            c += __shfl_down_sync(0xffffffffu, c, o);
                        running += __shfl_sync(0xffffffffu, c, 0);
                        break;
                    } else {
                        unsigned c = (unsigned)s64;
#pragma unroll
                        for (int o = 16; o; o >>= 1)
                            c += __shfl_down_sync(0xffffffffu, c, o);
                        running += __shfl_sync(0xffffffffu, c, 0);
                        idx -= 32;
                    }
                }
            }
            if (lane == 0) {
                atomicExch(&state[b], (2ULL << 32) | (running + total));
                s_base = (int)running;
                if (b == NB - 1) off[N_NODES] = (int)(running + total);
            }
        }
    }
    __syncthreads();
    int base = s_base;
    int woff = (w > 0) ? warpsum[w - 1] : 0;
    if (i < N_NODES) {
        int e = base + woff + inc - v;
        off[i] = e;
        cursor[i] = e;
        dis[i] = rsqrtf((float)(v + 1));
    }
}

__global__ void k_fill(const int* __restrict__ row, const int* __restrict__ col,
                       const float* __restrict__ dis,
                       int* __restrict__ cursor, int2* __restrict__ edge) {
    int e = blockIdx.x * blockDim.x + threadIdx.x;
    if (e >= N_EDGES) return;
    int r = row[e], c = col[e];
    int pos = atomicAdd(&cursor[c], 1);
    edge[pos] = make_int2(r, __float_as_int(dis[r] * dis[c]));
}

// ---------------- layer-0 pre-aggregate: xagg = Â x (128 ch, 2-wide, f32x2) --
__global__ __launch_bounds__(256) void k_agg0(const __half* __restrict__ xh,
                                              const int* __restrict__ off,
                                              const int2* __restrict__ edge,
                                              const float* __restrict__ dis,
                                              __half* __restrict__ xagg) {
    int nid  = blockIdx.x * 8 + (threadIdx.x >> 5);
    int lane = threadIdx.x & 31;
    if (nid >= N_NODES) return;
    float d  = dis[nid];
    float d2 = d * d;
    uint2 sv = ldg2(&xh[(size_t)nid * IN_CH + lane * 4]);
    float2 s0 = __half22float2(*(const __half2*)&sv.x);
    float2 s1 = __half22float2(*(const __half2*)&sv.y);
    u64t a0 = packf2(s0.x * d2, s0.y * d2);
    u64t a1 = packf2(s1.x * d2, s1.y * d2);
    int s = off[nid], e = off[nid + 1];
    int j = s;
    for (; j + 1 < e; j += 2) {
        int2 e0 = __ldg(&edge[j]);
        int2 e1 = __ldg(&edge[j + 1]);
        float w0 = __int_as_float(e0.y), w1 = __int_as_float(e1.y);
        u64t wd0 = packf2(w0, w0), wd1 = packf2(w1, w1);
        uint2 v0 = ldg2(&xh[(size_t)e0.x * IN_CH + lane * 4]);
        uint2 v1 = ldg2(&xh[(size_t)e1.x * IN_CH + lane * 4]);
        float2 f00 = __half22float2(*(const __half2*)&v0.x);
        float2 f01 = __half22float2(*(const __half2*)&v0.y);
        float2 f10 = __half22float2(*(const __half2*)&v1.x);
        float2 f11 = __half22float2(*(const __half2*)&v1.y);
        FMA_F32X2(a0, packf2(f00.x, f00.y), wd0, a0);
        FMA_F32X2(a1, packf2(f01.x, f01.y), wd0, a1);
        FMA_F32X2(a0, packf2(f10.x, f10.y), wd1, a0);
        FMA_F32X2(a1, packf2(f11.x, f11.y), wd1, a1);
    }
    if (j < e) {
        int2 e0 = __ldg(&edge[j]);
        float w0 = __int_as_float(e0.y);
        u64t wd0 = packf2(w0, w0);
        uint2 v0 = ldg2(&xh[(size_t)e0.x * IN_CH + lane * 4]);
        float2 f00 = __half22float2(*(const __half2*)&v0.x);
        float2 f01 = __half22float2(*(const __half2*)&v0.y);
        FMA_F32X2(a0, packf2(f00.x, f00.y), wd0, a0);
        FMA_F32X2(a1, packf2(f01.x, f01.y), wd0, a1);
    }
    float2 r0 = unpackf2(a0), r1 = unpackf2(a1);
    uint2 o;
    *(__half2*)&o.x = __floats2half2_rn(r0.x, r0.y);
    *(__half2*)&o.y = __floats2half2_rn(r1.x, r1.y);
    *(uint2*)&xagg[(size_t)nid * IN_CH + lane * 4] = o;
}

// ---------------- FP16 tensor-core GEMM, cp.async 2-stage double buffer ------
#define BM 128
#define BN 128
#define BK 32
#define SSTR 72
#define STG_H (BM * SSTR)                 // halves per stage (A or B)
#define GEMM_SMEM (4 * STG_H * 2)         // bytes: 2 stages x (A+B)

template <bool BIASRELU>
__global__ __launch_bounds__(256) void k_hgemm(const __half* __restrict__ A,
                                               const __half* __restrict__ Bt,
                                               __half* __restrict__ C,
                                               const float* __restrict__ bias,
                                               int M, int K) {
    extern __shared__ __half sh[];
    __half* AsBase = sh;
    __half* BsBase = sh + 2 * STG_H;
    const int tid  = threadIdx.x;
    const int warp = tid >> 5, lane = tid & 31;
    const int wm = (warp & 3) * 32;
    const int wn = (warp >> 2) * 64;
    const int r = lane >> 2, c = lane & 3;
    const int bm = blockIdx.y * BM;
    const int bn = blockIdx.x * BN;

    const int arow0 = (tid) >> 2,        acg0 = ((tid) & 3) * 8;
    const int arow1 = (tid + 256) >> 2,  acg1 = ((tid + 256) & 3) * 8;
    const int gm0 = bm + arow0, gm1 = bm + arow1;
    const int pb0 = (gm0 < M) ? 16 : 0, pb1 = (gm1 < M) ? 16 : 0;

    uint32_t sA = (uint32_t)__cvta_generic_to_shared(AsBase);
    uint32_t sB = (uint32_t)__cvta_generic_to_shared(BsBase);
    const uint32_t oA0 = (arow0 * SSTR + acg0) * 2;
    const uint32_t oA1 = (arow1 * SSTR + acg1) * 2;

    float acc[2][8][4];
#pragma unroll
    for (int mt = 0; mt < 2; mt++)
#pragma unroll
        for (int nt = 0; nt < 8; nt++)
#pragma unroll
            for (int q = 0; q < 4; q++) acc[mt][nt][q] = 0.0f;

    const int tiles = K / BK;

    {
        cp16(sA + oA0, &A[(size_t)gm0 * K + acg0], pb0);
        cp16(sA + oA1, &A[(size_t)gm1 * K + acg1], pb1);
        cp16(sB + oA0, &Bt[(size_t)(bn + arow0) * K + acg0], 16);
        cp16(sB + oA1, &Bt[(size_t)(bn + arow1) * K + acg1], 16);
        asm volatile("cp.async.commit_group;");
    }

    for (int t = 0; t < tiles; t++) {
        const int stg = t & 1;
        if (t + 1 < tiles) {
            const int kn = (t + 1) * BK;
            const uint32_t so = (stg ^ 1) * STG_H * 2;
            cp16(sA + so + oA0, &A[(size_t)gm0 * K + kn + acg0], pb0);
            cp16(sA + so + oA1, &A[(size_t)gm1 * K + kn + acg1], pb1);
            cp16(sB + so + oA0, &Bt[(size_t)(bn + arow0) * K + kn + acg0], 16);
            cp16(sB + so + oA1, &Bt[(size_t)(bn + arow1) * K + kn + acg1], 16);
            asm volatile("cp.async.commit_group;");
            asm volatile("cp.async.wait_group 1;");
        } else {
            asm volatile("cp.async.wait_group 0;");
        }
        __syncthreads();
        const __half* As = AsBase + stg * STG_H;
        const __half* Bs = BsBase + stg * STG_H;
#pragma unroll
        for (int ks = 0; ks < 2; ks++) {
            const int kk = ks * 16;
            uint32_t a[2][4];
#pragma unroll
            for (int mt = 0; mt < 2; mt++) {
                int base = wm + mt * 16;
                a[mt][0] = *(const uint32_t*)&As[(base + r    ) * SSTR + kk + 2 * c];
                a[mt][1] = *(const uint32_t*)&As[(base + r + 8) * SSTR + kk + 2 * c];
                a[mt][2] = *(const uint32_t*)&As[(base + r    ) * SSTR + kk + 8 + 2 * c];
                a[mt][3] = *(const uint32_t*)&As[(base + r + 8) * SSTR + kk + 8 + 2 * c];
            }
#pragma unroll
            for (int nt = 0; nt < 8; nt++) {
                uint32_t b0 = *(const uint32_t*)&Bs[(wn + nt * 8 + r) * SSTR + kk + 2 * c];
                uint32_t b1 = *(const uint32_t*)&Bs[(wn + nt * 8 + r) * SSTR + kk + 8 + 2 * c];
#pragma unroll
                for (int mt = 0; mt < 2; mt++) {
                    asm volatile(
                        "mma.sync.aligned.m16n8k16.row.col.f32.f16.f16.f32 "
                        "{%0,%1,%2,%3}, {%4,%5,%6,%7}, {%8,%9}, {%0,%1,%2,%3};"
                        : "+f"(acc[mt][nt][0]), "+f"(acc[mt][nt][1]),
                          "+f"(acc[mt][nt][2]), "+f"(acc[mt][nt][3])
                        : "r"(a[mt][0]), "r"(a[mt][1]), "r"(a[mt][2]), "r"(a[mt][3]),
                          "r"(b0), "r"(b1));
                }
            }
        }
        __syncthreads();
    }
#pragma unroll
    for (int mt = 0; mt < 2; mt++) {
        int row0 = bm + wm + mt * 16 + r;
#pragma unroll
        for (int nt = 0; nt < 8; nt++) {
            int cc = bn + wn + nt * 8 + 2 * c;
            float v0 = acc[mt][nt][0], v1 = acc[mt][nt][1];
            float v2 = acc[mt][nt][2], v3 = acc[mt][nt][3];
            if (BIASRELU) {
                float2 bv = *(const float2*)&bias[cc];
                v0 = fmaxf(v0 + bv.x, 0.f); v1 = fmaxf(v1 + bv.y, 0.f);
                v2 = fmaxf(v2 + bv.x, 0.f); v3 = fmaxf(v3 + bv.y, 0.f);
            }
            if (row0 < M)
                *(__half2*)&C[(size_t)row0 * HID + cc] = __floats2half2_rn(v0, v1);
            if (row0 + 8 < M)
                *(__half2*)&C[(size_t)(row0 + 8) * HID + cc] = __floats2half2_rn(v2, v3);
        }
    }
}

// ---------------- full aggregate (256 ch, dual-chain HFMA2, 2-wide) ----------
template <bool POOL>
__global__ __launch_bounds__(256) void k_agg_h(const __half* __restrict__ xw,
                                               const int* __restrict__ off,
                                               const int2* __restrict__ edge,
                                               const float* __restrict__ dis,
                                               const float* __restrict__ bias,
                                               __half* __restrict__ out,
                                               const int* __restrict__ batch,
                                               float* __restrict__ pooled) {
    int nid  = blockIdx.x * 8 + (threadIdx.x >> 5);
    int lane = threadIdx.x & 31;
    if (nid >= N_NODES) return;
    __half2 c0[4], c1[4];
    const __half2 hz = __float2half2_rn(0.0f);
#pragma unroll
    for (int q = 0; q < 4; q++) { c0[q] = hz; c1[q] = hz; }
    int s = off[nid], e = off[nid + 1];
    int j = s;
    for (; j + 1 < e; j += 2) {
        int2 e0 = __ldg(&edge[j]);
        int2 e1 = __ldg(&edge[j + 1]);
        __half2 w0 = __float2half2_rn(__int_as_float(e0.y));
        __half2 w1 = __float2half2_rn(__int_as_float(e1.y));
        uint4 v0 = ldg4(&xw[(size_t)e0.x * HID + lane * 8]);
        uint4 v1 = ldg4(&xw[(size_t)e1.x * HID + lane * 8]);
        c0[0] = __hfma2(*(const __half2*)&v0.x, w0, c0[0]);
        c0[1] = __hfma2(*(const __half2*)&v0.y, w0, c0[1]);
        c0[2] = __hfma2(*(const __half2*)&v0.z, w0, c0[2]);
        c0[3] = __hfma2(*(const __half2*)&v0.w, w0, c0[3]);
        c1[0] = __hfma2(*(const __half2*)&v1.x, w1, c1[0]);
        c1[1] = __hfma2(*(const __half2*)&v1.y, w1, c1[1]);
        c1[2] = __hfma2(*(const __half2*)&v1.z, w1, c1[2]);
        c1[3] = __hfma2(*(const __half2*)&v1.w, w1, c1[3]);
    }
    if (j < e) {
        int2 e0 = __ldg(&edge[j]);
        __half2 w0 = __float2half2_rn(__int_as_float(e0.y));
        uint4 v0 = ldg4(&xw[(size_t)e0.x * HID + lane * 8]);
        c0[0] = __hfma2(*(const __half2*)&v0.x, w0, c0[0]);
        c0[1] = __hfma2(*(const __half2*)&v0.y, w0, c0[1]);
        c0[2] = __hfma2(*(const __half2*)&v0.z, w0, c0[2]);
        c0[3] = __hfma2(*(const __half2*)&v0.w, w0, c0[3]);
    }
    float d = dis[nid];
    float d2 = d * d;
    float f[8], acc[8];
    uint4 sv = ldg4(&xw[(size_t)nid * HID + lane * 8]);
    h8f(sv, f);
#pragma unroll
    for (int q = 0; q < 4; q++) {
        float2 fa = __half22float2(c0[q]);
        float2 fb = __half22float2(c1[q]);
        acc[2 * q]     = fa.x + fb.x;
        acc[2 * q + 1] = fa.y + fb.y;
    }
    float4 b0 = *(const float4*)&bias[lane * 8];
    float4 b1 = *(const float4*)&bias[lane * 8 + 4];
    acc[0] = fmaf(f[0], d2, acc[0]) + b0.x; acc[1] = fmaf(f[1], d2, acc[1]) + b0.y;
    acc[2] = fmaf(f[2], d2, acc[2]) + b0.z; acc[3] = fmaf(f[3], d2, acc[3]) + b0.w;
    acc[4] = fmaf(f[4], d2, acc[4]) + b1.x; acc[5] = fmaf(f[5], d2, acc[5]) + b1.y;
    acc[6] = fmaf(f[6], d2, acc[6]) + b1.z; acc[7] = fmaf(f[7], d2, acc[7]) + b1.w;
#pragma unroll
    for (int q = 0; q < 8; q++) acc[q] = fmaxf(acc[q], 0.0f);
    if (POOL) {
        int bg = batch[nid];
        red_add_v4(&pooled[(size_t)bg * HID + lane * 8],
                   make_float4(acc[0], acc[1], acc[2], acc[3]));
        red_add_v4(&pooled[(size_t)bg * HID + lane * 8 + 4],
                   make_float4(acc[4], acc[5], acc[6], acc[7]));
    } else {
        uint4 o;
        *(__half2*)&o.x = __floats2half2_rn(acc[0], acc[1]);
        *(__half2*)&o.y = __floats2half2_rn(acc[2], acc[3]);
        *(__half2*)&o.z = __floats2half2_rn(acc[4], acc[5]);
        *(__half2*)&o.w = __floats2half2_rn(acc[6], acc[7]);
        *(uint4*)&out[(size_t)nid * HID + lane * 8] = o;
    }
}

// ---------------- FFN --------------------------------------------------------
__global__ __launch_bounds__(256) void k_ffn(const float* __restrict__ pooled,
                                             const float* __restrict__ counts,
                                             const float* __restrict__ Wf,
                                             const float* __restrict__ bf,
                                             const float* __restrict__ Wo,
                                             const float* __restrict__ bo,
                                             float* __restrict__ out) {
    int g = blockIdx.x;
    int t = threadIdx.x;
    __shared__ float prow[HID];
    __shared__ float red[HID];
    float inv = 1.0f / fmaxf(counts[g], 1.0f);
    prow[t] = pooled[g * HID + t] * inv;
    __syncthreads();
    float acc = bf[t];
#pragma unroll 8
    for (int k = 0; k < HID; k++) acc = fmaf(prow[k], Wf[k * HID + t], acc);
    red[t] = fmaxf(acc, 0.0f) * Wo[t];
    __syncthreads();
    for (int s = 128; s > 0; s >>= 1) {
        if (t < s) red[t] += red[t + s];
        __syncthreads();
    }
    if (t == 0) out[g] = red[0] + bo[0];
}

// ---------------- host side ---------------------------------------------------
extern "C" void kernel_launch(void* const* d_in, const int* in_sizes, int n_in,
                              void* d_out, int out_size) {
    const float* x    = (const float*)d_in[0];
    const int*   ei   = (const int*)d_in[1];
    const int*   batch= (const int*)d_in[2];
    const float* W1   = (const float*)d_in[3];
    const float* b1   = (const float*)d_in[4];
    const float* W2   = (const float*)d_in[5];
    const float* b2   = (const float*)d_in[6];
    const float* W3   = (const float*)d_in[7];
    const float* b3   = (const float*)d_in[8];
    const float* Wf   = (const float*)d_in[9];
    const float* bf   = (const float*)d_in[10];
    const float* Wo   = (const float*)d_in[11];
    const float* bo   = (const float*)d_in[12];
    float* out = (float*)d_out;

    const int* row = ei;
    const int* col = ei + N_EDGES;

    int *ideg, *off, *cursor;
    unsigned long long* state;
    int2* edge;
    float *dis, *pooled, *counts;
    __half *xh, *xagg, *Wt, *xw, *hA, *hB;
    cudaGetSymbolAddress((void**)&ideg,   g_ideg);
    cudaGetSymbolAddress((void**)&off,    g_off);
    cudaGetSymbolAddress((void**)&cursor, g_cursor);
    cudaGetSymbolAddress((void**)&state,  g_state);
    cudaGetSymbolAddress((void**)&edge,   g_edge);
    cudaGetSymbolAddress((void**)&dis,    g_dis);
    cudaGetSymbolAddress((void**)&xh,     g_xh);
    cudaGetSymbolAddress((void**)&xagg,   g_xagg);
    cudaGetSymbolAddress((void**)&Wt,     g_Wt);
    cudaGetSymbolAddress((void**)&xw,     g_xw);
    cudaGetSymbolAddress((void**)&hA,     g_hA);
    cudaGetSymbolAddress((void**)&hB,     g_hB);
    cudaGetSymbolAddress((void**)&pooled, g_pooled);
    cudaGetSymbolAddress((void**)&counts, g_counts);

    __half* Wt1 = Wt;
    __half* Wt2 = Wt + IN_CH * HID;
    __half* Wt3 = Wt2 + HID * HID;

    cudaFuncSetAttribute(k_hgemm<true>,
                         cudaFuncAttributeMaxDynamicSharedMemorySize, GEMM_SMEM);
    cudaFuncSetAttribute(k_hgemm<false>,
                         cudaFuncAttributeMaxDynamicSharedMemorySize, GEMM_SMEM);

    // ---- CSR build + prep (fused) ----
    k_zero<<<(N_GRAPHS * HID + 255) / 256, 256>>>(ideg, pooled, counts, state);
    k_front<<<(PREP_ITEMS + 255) / 256, 256>>>(col, ideg, batch, counts,
                                               x, xh, W1, W2, W3, Wt);
    k_scan_fused<<<NB, 1024>>>(ideg, off, cursor, dis, state);
    k_fill<<<(N_EDGES + 255) / 256, 256>>>(row, col, dis, cursor, edge);

    dim3 gemm_grid(HID / BN, (N_NODES + BM - 1) / BM);
    int node_blocks = (N_NODES + 7) / 8;

    // ---- layer 1: pre-aggregate (128 ch) then GEMM with bias+relu ----
    k_agg0<<<node_blocks, 256>>>(xh, off, edge, dis, xagg);
    k_hgemm<true><<<gemm_grid, 256, GEMM_SMEM>>>(xagg, Wt1, hA, b1, N_NODES, IN_CH);
    // ---- layer 2 ----
    k_hgemm<false><<<gemm_grid, 256, GEMM_SMEM>>>(hA, Wt2, xw, nullptr, N_NODES, HID);
    k_agg_h<false><<<node_blocks, 256>>>(xw, off, edge, dis, b2, hB, batch, pooled);
    // ---- layer 3 (pool fused) ----
    k_hgemm<false><<<gemm_grid, 256, GEMM_SMEM>>>(hB, Wt3, xw, nullptr, N_NODES, HID);
    k_agg_h<true><<<node_blocks, 256>>>(xw, off, edge, dis, b3, nullptr, batch, pooled);

    // ---- FFN ----
    k_ffn<<<N_GRAPHS, HID>>>(pooled, counts, Wf, bf, Wo, bo, out);
}

// round 10
// speedup vs baseline: 1.0010x; 1.0010x over previous
#include <cuda_runtime.h>
#include <cuda_fp16.h>
#include <cstdint>

#define N_NODES 50000
#define N_EDGES 800000
#define N_GRAPHS 256
#define IN_CH 128
#define HID 256
#define NB 49   // scan blocks of 1024

// ---------------- scratch (device globals; no allocation allowed) -------------
__device__ int   g_ideg[N_NODES];
__device__ int   g_off[N_NODES + 1];
__device__ int   g_cursor[N_NODES];
__device__ unsigned long long g_state[NB];       // decoupled-lookback state
__device__ __align__(16) int2 g_edge[N_EDGES];   // {src, w-as-int}
__device__ float g_dis[N_NODES];
__device__ __align__(16) __half g_xh[(size_t)N_NODES * IN_CH];
__device__ __align__(16) __half g_xagg[(size_t)N_NODES * IN_CH];
__device__ __align__(16) __half g_Wt[(IN_CH + HID + HID) * HID];
__device__ __align__(16) __half g_xw[(size_t)N_NODES * HID];
__device__ __align__(16) __half g_hA[(size_t)N_NODES * HID];
__device__ __align__(16) __half g_hB[(size_t)N_NODES * HID];
__device__ float g_pooled[N_GRAPHS * HID];
__device__ float g_counts[N_GRAPHS];

// ---------------- helpers ----------------------------------------------------
__device__ __forceinline__ void red_add_v4(float* addr, float4 v) {
    asm volatile("red.global.add.v4.f32 [%0], {%1,%2,%3,%4};"
                 :: "l"(addr), "f"(v.x), "f"(v.y), "f"(v.z), "f"(v.w)
                 : "memory");
}

__device__ __forceinline__ void h8f(uint4 v, float* f) {
    float2 p0 = __half22float2(*(const __half2*)&v.x);
    float2 p1 = __half22float2(*(const __half2*)&v.y);
    float2 p2 = __half22float2(*(const __half2*)&v.z);
    float2 p3 = __half22float2(*(const __half2*)&v.w);
    f[0] = p0.x; f[1] = p0.y; f[2] = p1.x; f[3] = p1.y;
    f[4] = p2.x; f[5] = p2.y; f[6] = p3.x; f[7] = p3.y;
}

typedef unsigned long long u64t;
__device__ __forceinline__ u64t packf2(float x, float y) {
    u64t u; asm("mov.b64 %0, {%1,%2};" : "=l"(u) : "f"(x), "f"(y)); return u;
}
__device__ __forceinline__ float2 unpackf2(u64t u) {
    float2 f; asm("mov.b64 {%0,%1}, %2;" : "=f"(f.x), "=f"(f.y) : "l"(u)); return f;
}
#define FMA_F32X2(d, a, b, c) \
    asm("fma.rn.f32x2 %0, %1, %2, %3;" : "=l"(d) : "l"(a), "l"(b), "l"(c))

__device__ __forceinline__ void cp16(uint32_t saddr, const void* g, int pbytes) {
    asm volatile("cp.async.ca.shared.global [%0], [%1], 16, %2;"
                 :: "r"(saddr), "l"(g), "r"(pbytes));
}

// ---------------- front kernel: degree/batch counts + fp16 prep, fused -------
#define XF4   (N_NODES * IN_CH / 4)
#define W1E   (IN_CH * HID)
#define W23E  (HID * HID)
#define PREP_ITEMS (XF4 + W1E + 2 * W23E)
__global__ void k_front(const int* __restrict__ col, int* __restrict__ ideg,
                        const int* __restrict__ batch, float* __restrict__ counts,
                        const float* __restrict__ x, __half* __restrict__ xh,
                        const float* __restrict__ W1, const float* __restrict__ W2,
                        const float* __restrict__ W3, __half* __restrict__ Wt) {
    int i = blockIdx.x * blockDim.x + threadIdx.x;
    if (i < N_EDGES) atomicAdd(&ideg[col[i]], 1);
    if (i < N_NODES) atomicAdd(&counts[batch[i]], 1.0f);
    int p = i;
    if (p < XF4) {
        float4 v = ((const float4*)x)[p];
        ((__half2*)xh)[p * 2]     = __floats2half2_rn(v.x, v.y);
        ((__half2*)xh)[p * 2 + 1] = __floats2half2_rn(v.z, v.w);
    } else {
        p -= XF4;
        if (p < W1E) {
            int k = p >> 8, n = p & 255;
            Wt[(size_t)n * IN_CH + k] = __float2half(W1[p]);
        } else {
            p -= W1E;
            if (p < W23E) {
                int k = p >> 8, n = p & 255;
                Wt[W1E + (size_t)n * HID + k] = __float2half(W2[p]);
            } else {
                p -= W23E;
                if (p < W23E) {
                    int k = p >> 8, n = p & 255;
                    Wt[W1E + W23E + (size_t)n * HID + k] = __float2half(W3[p]);
                }
            }
        }
    }
}

// ---------------- CSR build ---------------------------------------------------
__global__ void k_zero(int* ideg, float* pooled, float* counts,
                       unsigned long long* state) {
    int i = blockIdx.x * blockDim.x + threadIdx.x;
    if (i < N_NODES) ideg[i] = 0;
    if (i < N_GRAPHS * HID) pooled[i] = 0.0f;
    if (i < N_GRAPHS) counts[i] = 0.0f;
    if (i < NB) state[i] = 0ULL;
}

// single-kernel exclusive scan with warp-parallel decoupled lookback.
__global__ __launch_bounds__(1024) void k_scan_fused(const int* __restrict__ ideg,
                                                     int* __restrict__ off,
                                                     int* __restrict__ cursor,
                                                     float* __restrict__ dis,
                                                     unsigned long long* __restrict__ state) {
    __shared__ int warpsum[32];
    __shared__ int s_base;
    const int b = blockIdx.x, t = threadIdx.x;
    const int lane = t & 31, w = t >> 5;
    int i = b * 1024 + t;
    int v = (i < N_NODES) ? ideg[i] : 0;
    int inc = v;
#pragma unroll
    for (int s = 1; s < 32; s <<= 1) {
        int u = __shfl_up_sync(0xffffffffu, inc, s);
        if (lane >= s) inc += u;
    }
    if (lane == 31) warpsum[w] = inc;
    __syncthreads();
    if (w == 0) {
        int wi = warpsum[lane];
#pragma unroll
        for (int s = 1; s < 32; s <<= 1) {
            int u = __shfl_up_sync(0xffffffffu, wi, s);
            if (lane >= s) wi += u;
        }
        warpsum[lane] = wi;
        unsigned total = (unsigned)__shfl_sync(0xffffffffu, wi, 31);
        if (b == 0) {
            if (lane == 0) {
                atomicExch(&state[0], (2ULL << 32) | total);
                s_base = 0;
            }
        } else {
            if (lane == 0) atomicExch(&state[b], (1ULL << 32) | total);
            unsigned running = 0;
            int idx = b - 1;
            while (true) {
                int ii = idx - lane;
                unsigned long long s64 = (ii >= 0)
                    ? atomicAdd(&state[ii], 0ULL) : (2ULL << 32);
                unsigned flag = (unsigned)(s64 >> 32);
                if (__all_sync(0xffffffffu, flag != 0)) {
                    unsigned pm = __ballot_sync(0xffffffffu, flag == 2u);
                    if (pm) {
                        int k = __ffs(pm) - 1;
                        unsigned c = (lane <= k) ? (unsigned)s64 : 0u;
#pragma unroll
                        for (int o = 16; o; o >>= 1)
                            c += __shfl_down_sync(0xffffffffu, c, o);
                        running += __shfl_sync(0xffffffffu, c, 0);
                        break;
                    } else {
                        unsigned c = (unsigned)s64;
#pragma unroll
                        for (int o = 16; o; o >>= 1)
                            c += __shfl_down_sync(0xffffffffu, c, o);
                        running += __shfl_sync(0xffffffffu, c, 0);
                        idx -= 32;
                    }
                }
            }
            if (lane == 0) {
                atomicExch(&state[b], (2ULL << 32) | (running + total));
                s_base = (int)running;
                if (b == NB - 1) off[N_NODES] = (int)(running + total);
            }
        }
    }
    __syncthreads();
    int base = s_base;
    int woff = (w > 0) ? warpsum[w - 1] : 0;
    if (i < N_NODES) {
        int e = base + woff + inc - v;
        off[i] = e;
        cursor[i] = e;
        dis[i] = rsqrtf((float)(v + 1));
    }
}

__global__ void k_fill(const int* __restrict__ row, const int* __restrict__ col,
                       const float* __restrict__ dis,
                       int* __restrict__ cursor, int2* __restrict__ edge) {
    int e = blockIdx.x * blockDim.x + threadIdx.x;
    if (e >= N_EDGES) return;
    int r = row[e], c = col[e];
    int pos = atomicAdd(&cursor[c], 1);
    edge[pos] = make_int2(r, __float_as_int(dis[r] * dis[c]));
}

// ---------------- layer-0 pre-aggregate: xagg = Â x (128 ch, 2-wide, f32x2) --
__global__ __launch_bounds__(256) void k_agg0(const __half* __restrict__ xh,
                                              const int* __restrict__ off,
                                              const int2* __restrict__ edge,
                                              const float* __restrict__ dis,
                                              __half* __restrict__ xagg) {
    int nid  = blockIdx.x * 8 + (threadIdx.x >> 5);
    int lane = threadIdx.x & 31;
    if (nid >= N_NODES) return;
    float d  = dis[nid];
    float d2 = d * d;
    uint2 sv = *(const uint2*)&xh[(size_t)nid * IN_CH + lane * 4];
    float2 s0 = __half22float2(*(const __half2*)&sv.x);
    float2 s1 = __half22float2(*(const __half2*)&sv.y);
    u64t a0 = packf2(s0.x * d2, s0.y * d2);
    u64t a1 = packf2(s1.x * d2, s1.y * d2);
    int s = off[nid], e = off[nid + 1];
    int j = s;
    for (; j + 1 < e; j += 2) {
        int2 e0 = __ldg(&edge[j]);
        int2 e1 = __ldg(&edge[j + 1]);
        float w0 = __int_as_float(e0.y), w1 = __int_as_float(e1.y);
        u64t wd0 = packf2(w0, w0), wd1 = packf2(w1, w1);
        uint2 v0 = *(const uint2*)&xh[(size_t)e0.x * IN_CH + lane * 4];
        uint2 v1 = *(const uint2*)&xh[(size_t)e1.x * IN_CH + lane * 4];
        float2 f00 = __half22float2(*(const __half2*)&v0.x);
        float2 f01 = __half22float2(*(const __half2*)&v0.y);
        float2 f10 = __half22float2(*(const __half2*)&v1.x);
        float2 f11 = __half22float2(*(const __half2*)&v1.y);
        FMA_F32X2(a0, packf2(f00.x, f00.y), wd0, a0);
        FMA_F32X2(a1, packf2(f01.x, f01.y), wd0, a1);
        FMA_F32X2(a0, packf2(f10.x, f10.y), wd1, a0);
        FMA_F32X2(a1, packf2(f11.x, f11.y), wd1, a1);
    }
    if (j < e) {
        int2 e0 = __ldg(&edge[j]);
        float w0 = __int_as_float(e0.y);
        u64t wd0 = packf2(w0, w0);
        uint2 v0 = *(const uint2*)&xh[(size_t)e0.x * IN_CH + lane * 4];
        float2 f00 = __half22float2(*(const __half2*)&v0.x);
        float2 f01 = __half22float2(*(const __half2*)&v0.y);
        FMA_F32X2(a0, packf2(f00.x, f00.y), wd0, a0);
        FMA_F32X2(a1, packf2(f01.x, f01.y), wd0, a1);
    }
    float2 r0 = unpackf2(a0), r1 = unpackf2(a1);
    uint2 o;
    *(__half2*)&o.x = __floats2half2_rn(r0.x, r0.y);
    *(__half2*)&o.y = __floats2half2_rn(r1.x, r1.y);
    *(uint2*)&xagg[(size_t)nid * IN_CH + lane * 4] = o;
}

// ---------------- FP16 tensor-core GEMM, cp.async 2-stage double buffer ------
#define BM 128
#define BN 128
#define BK 32
#define SSTR 72
#define STG_H (BM * SSTR)                 // halves per stage (A or B)
#define GEMM_SMEM (4 * STG_H * 2)         // bytes: 2 stages x (A+B)

template <bool BIASRELU>
__global__ __launch_bounds__(256) void k_hgemm(const __half* __restrict__ A,
                                               const __half* __restrict__ Bt,
                                               __half* __restrict__ C,
                                               const float* __restrict__ bias,
                                               int M, int K) {
    extern __shared__ __half sh[];
    __half* AsBase = sh;
    __half* BsBase = sh + 2 * STG_H;
    const int tid  = threadIdx.x;
    const int warp = tid >> 5, lane = tid & 31;
    const int wm = (warp & 3) * 32;
    const int wn = (warp >> 2) * 64;
    const int r = lane >> 2, c = lane & 3;
    const int bm = blockIdx.y * BM;
    const int bn = blockIdx.x * BN;

    const int arow0 = (tid) >> 2,        acg0 = ((tid) & 3) * 8;
    const int arow1 = (tid + 256) >> 2,  acg1 = ((tid + 256) & 3) * 8;
    const int gm0 = bm + arow0, gm1 = bm + arow1;
    const int pb0 = (gm0 < M) ? 16 : 0, pb1 = (gm1 < M) ? 16 : 0;

    uint32_t sA = (uint32_t)__cvta_generic_to_shared(AsBase);
    uint32_t sB = (uint32_t)__cvta_generic_to_shared(BsBase);
    const uint32_t oA0 = (arow0 * SSTR + acg0) * 2;
    const uint32_t oA1 = (arow1 * SSTR + acg1) * 2;

    float acc[2][8][4];
#pragma unroll
    for (int mt = 0; mt < 2; mt++)
#pragma unroll
        for (int nt = 0; nt < 8; nt++)
#pragma unroll
            for (int q = 0; q < 4; q++) acc[mt][nt][q] = 0.0f;

    const int tiles = K / BK;

    {
        cp16(sA + oA0, &A[(size_t)gm0 * K + acg0], pb0);
        cp16(sA + oA1, &A[(size_t)gm1 * K + acg1], pb1);
        cp16(sB + oA0, &Bt[(size_t)(bn + arow0) * K + acg0], 16);
        cp16(sB + oA1, &Bt[(size_t)(bn + arow1) * K + acg1], 16);
        asm volatile("cp.async.commit_group;");
    }

    for (int t = 0; t < tiles; t++) {
        const int stg = t & 1;
        if (t + 1 < tiles) {
            const int kn = (t + 1) * BK;
            const uint32_t so = (stg ^ 1) * STG_H * 2;
            cp16(sA + so + oA0, &A[(size_t)gm0 * K + kn + acg0], pb0);
            cp16(sA + so + oA1, &A[(size_t)gm1 * K + kn + acg1], pb1);
            cp16(sB + so + oA0, &Bt[(size_t)(bn + arow0) * K + kn + acg0], 16);
            cp16(sB + so + oA1, &Bt[(size_t)(bn + arow1) * K + kn + acg1], 16);
            asm volatile("cp.async.commit_group;");
            asm volatile("cp.async.wait_group 1;");
        } else {
            asm volatile("cp.async.wait_group 0;");
        }
        __syncthreads();
        const __half* As = AsBase + stg * STG_H;
        const __half* Bs = BsBase + stg * STG_H;
#pragma unroll
        for (int ks = 0; ks < 2; ks++) {
            const int kk = ks * 16;
            uint32_t a[2][4];
#pragma unroll
            for (int mt = 0; mt < 2; mt++) {
                int base = wm + mt * 16;
                a[mt][0] = *(const uint32_t*)&As[(base + r    ) * SSTR + kk + 2 * c];
                a[mt][1] = *(const uint32_t*)&As[(base + r + 8) * SSTR + kk + 2 * c];
                a[mt][2] = *(const uint32_t*)&As[(base + r    ) * SSTR + kk + 8 + 2 * c];
                a[mt][3] = *(const uint32_t*)&As[(base + r + 8) * SSTR + kk + 8 + 2 * c];
            }
#pragma unroll
            for (int nt = 0; nt < 8; nt++) {
                uint32_t b0 = *(const uint32_t*)&Bs[(wn + nt * 8 + r) * SSTR + kk + 2 * c];
                uint32_t b1 = *(const uint32_t*)&Bs[(wn + nt * 8 + r) * SSTR + kk + 8 + 2 * c];
#pragma unroll
                for (int mt = 0; mt < 2; mt++) {
                    asm volatile(
                        "mma.sync.aligned.m16n8k16.row.col.f32.f16.f16.f32 "
                        "{%0,%1,%2,%3}, {%4,%5,%6,%7}, {%8,%9}, {%0,%1,%2,%3};"
                        : "+f"(acc[mt][nt][0]), "+f"(acc[mt][nt][1]),
                          "+f"(acc[mt][nt][2]), "+f"(acc[mt][nt][3])
                        : "r"(a[mt][0]), "r"(a[mt][1]), "r"(a[mt][2]), "r"(a[mt][3]),
                          "r"(b0), "r"(b1));
                }
            }
        }
        __syncthreads();
    }
#pragma unroll
    for (int mt = 0; mt < 2; mt++) {
        int row0 = bm + wm + mt * 16 + r;
#pragma unroll
        for (int nt = 0; nt < 8; nt++) {
            int cc = bn + wn + nt * 8 + 2 * c;
            float v0 = acc[mt][nt][0], v1 = acc[mt][nt][1];
            float v2 = acc[mt][nt][2], v3 = acc[mt][nt][3];
            if (BIASRELU) {
                float2 bv = *(const float2*)&bias[cc];
                v0 = fmaxf(v0 + bv.x, 0.f); v1 = fmaxf(v1 + bv.y, 0.f);
                v2 = fmaxf(v2 + bv.x, 0.f); v3 = fmaxf(v3 + bv.y, 0.f);
            }
            if (row0 < M)
                *(__half2*)&C[(size_t)row0 * HID + cc] = __floats2half2_rn(v0, v1);
            if (row0 + 8 < M)
                *(__half2*)&C[(size_t)(row0 + 8) * HID + cc] = __floats2half2_rn(v2, v3);
        }
    }
}

// ---------------- full aggregate (256 ch, dual-chain HFMA2, 2-wide) ----------
template <bool POOL>
__global__ __launch_bounds__(256) void k_agg_h(const __half* __restrict__ xw,
                                               const int* __restrict__ off,
                                               const int2* __restrict__ edge,
                                               const float* __restrict__ dis,
                                               const float* __restrict__ bias,
                                               __half* __restrict__ out,
                                               const int* __restrict__ batch,
                                               float* __restrict__ pooled) {
    int nid  = blockIdx.x * 8 + (threadIdx.x >> 5);
    int lane = threadIdx.x & 31;
    if (nid >= N_NODES) return;
    __half2 c0[4], c1[4];
    const __half2 hz = __float2half2_rn(0.0f);
#pragma unroll
    for (int q = 0; q < 4; q++) { c0[q] = hz; c1[q] = hz; }
    int s = off[nid], e = off[nid + 1];
    int j = s;
    for (; j + 1 < e; j += 2) {
        int2 e0 = __ldg(&edge[j]);
        int2 e1 = __ldg(&edge[j + 1]);
        __half2 w0 = __float2half2_rn(__int_as_float(e0.y));
        __half2 w1 = __float2half2_rn(__int_as_float(e1.y));
        uint4 v0 = *(const uint4*)&xw[(size_t)e0.x * HID + lane * 8];
        uint4 v1 = *(const uint4*)&xw[(size_t)e1.x * HID + lane * 8];
        c0[0] = __hfma2(*(const __half2*)&v0.x, w0, c0[0]);
        c0[1] = __hfma2(*(const __half2*)&v0.y, w0, c0[1]);
        c0[2] = __hfma2(*(const __half2*)&v0.z, w0, c0[2]);
        c0[3] = __hfma2(*(const __half2*)&v0.w, w0, c0[3]);
        c1[0] = __hfma2(*(const __half2*)&v1.x, w1, c1[0]);
        c1[1] = __hfma2(*(const __half2*)&v1.y, w1, c1[1]);
        c1[2] = __hfma2(*(const __half2*)&v1.z, w1, c1[2]);
        c1[3] = __hfma2(*(const __half2*)&v1.w, w1, c1[3]);
    }
    if (j < e) {
        int2 e0 = __ldg(&edge[j]);
        __half2 w0 = __float2half2_rn(__int_as_float(e0.y));
        uint4 v0 = *(const uint4*)&xw[(size_t)e0.x * HID + lane * 8];
        c0[0] = __hfma2(*(const __half2*)&v0.x, w0, c0[0]);
        c0[1] = __hfma2(*(const __half2*)&v0.y, w0, c0[1]);
        c0[2] = __hfma2(*(const __half2*)&v0.z, w0, c0[2]);
        c0[3] = __hfma2(*(const __half2*)&v0.w, w0, c0[3]);
    }
    float d = dis[nid];
    float d2 = d * d;
    float f[8], acc[8];
    uint4 sv = *(const uint4*)&xw[(size_t)nid * HID + lane * 8];
    h8f(sv, f);
#pragma unroll
    for (int q = 0; q < 4; q++) {
        float2 fa = __half22float2(c0[q]);
        float2 fb = __half22float2(c1[q]);
        acc[2 * q]     = fa.x + fb.x;
        acc[2 * q + 1] = fa.y + fb.y;
    }
    float4 b0 = *(const float4*)&bias[lane * 8];
    float4 b1 = *(const float4*)&bias[lane * 8 + 4];
    acc[0] = fmaf(f[0], d2, acc[0]) + b0.x; acc[1] = fmaf(f[1], d2, acc[1]) + b0.y;
    acc[2] = fmaf(f[2], d2, acc[2]) + b0.z; acc[3] = fmaf(f[3], d2, acc[3]) + b0.w;
    acc[4] = fmaf(f[4], d2, acc[4]) + b1.x; acc[5] = fmaf(f[5], d2, acc[5]) + b1.y;
    acc[6] = fmaf(f[6], d2, acc[6]) + b1.z; acc[7] = fmaf(f[7], d2, acc[7]) + b1.w;
#pragma unroll
    for (int q = 0; q < 8; q++) acc[q] = fmaxf(acc[q], 0.0f);
    if (POOL) {
        int bg = batch[nid];
        red_add_v4(&pooled[(size_t)bg * HID + lane * 8],
                   make_float4(acc[0], acc[1], acc[2], acc[3]));
        red_add_v4(&pooled[(size_t)bg * HID + lane * 8 + 4],
                   make_float4(acc[4], acc[5], acc[6], acc[7]));
    } else {
        uint4 o;
        *(__half2*)&o.x = __floats2half2_rn(acc[0], acc[1]);
        *(__half2*)&o.y = __floats2half2_rn(acc[2], acc[3]);
        *(__half2*)&o.z = __floats2half2_rn(acc[4], acc[5]);
        *(__half2*)&o.w = __floats2half2_rn(acc[6], acc[7]);
        *(uint4*)&out[(size_t)nid * HID + lane * 8] = o;
    }
}

// ---------------- FFN --------------------------------------------------------
__global__ __launch_bounds__(256) void k_ffn(const float* __restrict__ pooled,
                                             const float* __restrict__ counts,
                                             const float* __restrict__ Wf,
                                             const float* __restrict__ bf,
                                             const float* __restrict__ Wo,
                                             const float* __restrict__ bo,
                                             float* __restrict__ out) {
    int g = blockIdx.x;
    int t = threadIdx.x;
    __shared__ float prow[HID];
    __shared__ float red[HID];
    float inv = 1.0f / fmaxf(counts[g], 1.0f);
    prow[t] = pooled[g * HID + t] * inv;
    __syncthreads();
    float acc = bf[t];
#pragma unroll 8
    for (int k = 0; k < HID; k++) acc = fmaf(prow[k], Wf[k * HID + t], acc);
    red[t] = fmaxf(acc, 0.0f) * Wo[t];
    __syncthreads();
    for (int s = 128; s > 0; s >>= 1) {
        if (t < s) red[t] += red[t + s];
        __syncthreads();
    }
    if (t == 0) out[g] = red[0] + bo[0];
}

// ---------------- host side ---------------------------------------------------
extern "C" void kernel_launch(void* const* d_in, const int* in_sizes, int n_in,
                              void* d_out, int out_size) {
    const float* x    = (const float*)d_in[0];
    const int*   ei   = (const int*)d_in[1];
    const int*   batch= (const int*)d_in[2];
    const float* W1   = (const float*)d_in[3];
    const float* b1   = (const float*)d_in[4];
    const float* W2   = (const float*)d_in[5];
    const float* b2   = (const float*)d_in[6];
    const float* W3   = (const float*)d_in[7];
    const float* b3   = (const float*)d_in[8];
    const float* Wf   = (const float*)d_in[9];
    const float* bf   = (const float*)d_in[10];
    const float* Wo   = (const float*)d_in[11];
    const float* bo   = (const float*)d_in[12];
    float* out = (float*)d_out;

    const int* row = ei;
    const int* col = ei + N_EDGES;

    int *ideg, *off, *cursor;
    unsigned long long* state;
    int2* edge;
    float *dis, *pooled, *counts;
    __half *xh, *xagg, *Wt, *xw, *hA, *hB;
    cudaGetSymbolAddress((void**)&ideg,   g_ideg);
    cudaGetSymbolAddress((void**)&off,    g_off);
    cudaGetSymbolAddress((void**)&cursor, g_cursor);
    cudaGetSymbolAddress((void**)&state,  g_state);
    cudaGetSymbolAddress((void**)&edge,   g_edge);
    cudaGetSymbolAddress((void**)&dis,    g_dis);
    cudaGetSymbolAddress((void**)&xh,     g_xh);
    cudaGetSymbolAddress((void**)&xagg,   g_xagg);
    cudaGetSymbolAddress((void**)&Wt,     g_Wt);
    cudaGetSymbolAddress((void**)&xw,     g_xw);
    cudaGetSymbolAddress((void**)&hA,     g_hA);
    cudaGetSymbolAddress((void**)&hB,     g_hB);
    cudaGetSymbolAddress((void**)&pooled, g_pooled);
    cudaGetSymbolAddress((void**)&counts, g_counts);

    __half* Wt1 = Wt;
    __half* Wt2 = Wt + IN_CH * HID;
    __half* Wt3 = Wt2 + HID * HID;

    cudaFuncSetAttribute(k_hgemm<true>,
                         cudaFuncAttributeMaxDynamicSharedMemorySize, GEMM_SMEM);
    cudaFuncSetAttribute(k_hgemm<false>,
                         cudaFuncAttributeMaxDynamicSharedMemorySize, GEMM_SMEM);

    // ---- CSR build + prep (fused) ----
    k_zero<<<(N_GRAPHS * HID + 255) / 256, 256>>>(ideg, pooled, counts, state);
    k_front<<<(PREP_ITEMS + 255) / 256, 256>>>(col, ideg, batch, counts,
                                               x, xh, W1, W2, W3, Wt);
    k_scan_fused<<<NB, 1024>>>(ideg, off, cursor, dis, state);
    k_fill<<<(N_EDGES + 255) / 256, 256>>>(row, col, dis, cursor, edge);

    dim3 gemm_grid(HID / BN, (N_NODES + BM - 1) / BM);
    int node_blocks = (N_NODES + 7) / 8;

    // ---- layer 1: pre-aggregate (128 ch) then GEMM with bias+relu ----
    k_agg0<<<node_blocks, 256>>>(xh, off, edge, dis, xagg);
    k_hgemm<true><<<gemm_grid, 256, GEMM_SMEM>>>(xagg, Wt1, hA, b1, N_NODES, IN_CH);
    // ---- layer 2 ----
    k_hgemm<false><<<gemm_grid, 256, GEMM_SMEM>>>(hA, Wt2, xw, nullptr, N_NODES, HID);
    k_agg_h<false><<<node_blocks, 256>>>(xw, off, edge, dis, b2, hB, batch, pooled);
    // ---- layer 3 (pool fused) ----
    k_hgemm<false><<<gemm_grid, 256, GEMM_SMEM>>>(hB, Wt3, xw, nullptr, N_NODES, HID);
    k_agg_h<true><<<node_blocks, 256>>>(xw, off, edge, dis, b3, nullptr, batch, pooled);

    // ---- FFN ----
    k_ffn<<<N_GRAPHS, HID>>>(pooled, counts, Wf, bf, Wo, bo, out);
}

// round 11
// speedup vs baseline: 1.3646x; 1.3633x over previous
#include <cuda_runtime.h>
#include <cuda_fp16.h>
#include <cstdint>

#define N_NODES 50000
#define N_EDGES 800000
#define N_GRAPHS 256
#define IN_CH 128
#define HID 256
#define NB 49   // scan blocks of 1024

// ---------------- scratch (device globals; no allocation allowed) -------------
__device__ int   g_ideg[N_NODES];
__device__ int   g_off[N_NODES + 1];
__device__ int   g_cursor[N_NODES];
__device__ unsigned long long g_state[NB];       // decoupled-lookback state
__device__ __align__(16) int2 g_edge[N_EDGES];   // {src, w-as-int}
__device__ float g_dis[N_NODES];
__device__ __align__(16) __half g_xh[(size_t)N_NODES * IN_CH];
__device__ __align__(16) __half g_xagg[(size_t)N_NODES * IN_CH];
__device__ __align__(16) __half g_Wt[(IN_CH + HID + HID) * HID];
__device__ __align__(16) __half g_xw[(size_t)N_NODES * HID];
__device__ __align__(16) __half g_hA[(size_t)N_NODES * HID];
__device__ __align__(16) __half g_hB[(size_t)N_NODES * HID];
__device__ float g_pooled[N_GRAPHS * HID];
__device__ float g_counts[N_GRAPHS];

// ---------------- helpers ----------------------------------------------------
__device__ __forceinline__ void red_add_v4(float* addr, float4 v) {
    asm volatile("red.global.add.v4.f32 [%0], {%1,%2,%3,%4};"
                 :: "l"(addr), "f"(v.x), "f"(v.y), "f"(v.z), "f"(v.w)
                 : "memory");
}

__device__ __forceinline__ void h8f(uint4 v, float* f) {
    float2 p0 = __half22float2(*(const __half2*)&v.x);
    float2 p1 = __half22float2(*(const __half2*)&v.y);
    float2 p2 = __half22float2(*(const __half2*)&v.z);
    float2 p3 = __half22float2(*(const __half2*)&v.w);
    f[0] = p0.x; f[1] = p0.y; f[2] = p1.x; f[3] = p1.y;
    f[4] = p2.x; f[5] = p2.y; f[6] = p3.x; f[7] = p3.y;
}

typedef unsigned long long u64t;
__device__ __forceinline__ u64t packf2(float x, float y) {
    u64t u; asm("mov.b64 %0, {%1,%2};" : "=l"(u) : "f"(x), "f"(y)); return u;
}
__device__ __forceinline__ float2 unpackf2(u64t u) {
    float2 f; asm("mov.b64 {%0,%1}, %2;" : "=f"(f.x), "=f"(f.y) : "l"(u)); return f;
}
#define FMA_F32X2(d, a, b, c) \
    asm("fma.rn.f32x2 %0, %1, %2, %3;" : "=l"(d) : "l"(a), "l"(b), "l"(c))

__device__ __forceinline__ void cp16(uint32_t saddr, const void* g, int pbytes) {
    asm volatile("cp.async.ca.shared.global [%0], [%1], 16, %2;"
                 :: "r"(saddr), "l"(g), "r"(pbytes));
}

// ---------------- fused prep: x->fp16, W1/W2/W3 -> transposed fp16 -----------
#define XF4   (N_NODES * IN_CH / 4)
#define W1E   (IN_CH * HID)
#define W23E  (HID * HID)
__global__ void k_prep(const float* __restrict__ x, __half* __restrict__ xh,
                       const float* __restrict__ W1, const float* __restrict__ W2,
                       const float* __restrict__ W3, __half* __restrict__ Wt) {
    int i = blockIdx.x * blockDim.x + threadIdx.x;
    if (i < XF4) {
        float4 v = ((const float4*)x)[i];
        ((__half2*)xh)[i * 2]     = __floats2half2_rn(v.x, v.y);
        ((__half2*)xh)[i * 2 + 1] = __floats2half2_rn(v.z, v.w);
        return;
    }
    i -= XF4;
    if (i < W1E) {
        int k = i >> 8, n = i & 255;
        Wt[(size_t)n * IN_CH + k] = __float2half(W1[i]);
        return;
    }
    i -= W1E;
    if (i < W23E) {
        int k = i >> 8, n = i & 255;
        Wt[W1E + (size_t)n * HID + k] = __float2half(W2[i]);
        return;
    }
    i -= W23E;
    if (i < W23E) {
        int k = i >> 8, n = i & 255;
        Wt[W1E + W23E + (size_t)n * HID + k] = __float2half(W3[i]);
    }
}

// ---------------- CSR build ---------------------------------------------------
__global__ void k_zero(int* ideg, float* pooled, float* counts,
                       unsigned long long* state) {
    int i = blockIdx.x * blockDim.x + threadIdx.x;
    if (i < N_NODES) ideg[i] = 0;
    if (i < N_GRAPHS * HID) pooled[i] = 0.0f;
    if (i < N_GRAPHS) counts[i] = 0.0f;
    if (i < NB) state[i] = 0ULL;
}

__global__ void k_count(const int* __restrict__ col, int* __restrict__ ideg,
                        const int* __restrict__ batch, float* __restrict__ counts) {
    int e = blockIdx.x * blockDim.x + threadIdx.x;
    if (e < N_EDGES) atomicAdd(&ideg[col[e]], 1);
    if (e < N_NODES) atomicAdd(&counts[batch[e]], 1.0f);
}

// single-kernel exclusive scan with warp-parallel decoupled lookback.
__global__ __launch_bounds__(1024) void k_scan_fused(const int* __restrict__ ideg,
                                                     int* __restrict__ off,
                                                     int* __restrict__ cursor,
                                                     float* __restrict__ dis,
                                                     unsigned long long* __restrict__ state) {
    __shared__ int warpsum[32];
    __shared__ int s_base;
    const int b = blockIdx.x, t = threadIdx.x;
    const int lane = t & 31, w = t >> 5;
    int i = b * 1024 + t;
    int v = (i < N_NODES) ? ideg[i] : 0;
    int inc = v;
#pragma unroll
    for (int s = 1; s < 32; s <<= 1) {
        int u = __shfl_up_sync(0xffffffffu, inc, s);
        if (lane >= s) inc += u;
    }
    if (lane == 31) warpsum[w] = inc;
    __syncthreads();
    if (w == 0) {
        int wi = warpsum[lane];
#pragma unroll
        for (int s = 1; s < 32; s <<= 1) {
            int u = __shfl_up_sync(0xffffffffu, wi, s);
            if (lane >= s) wi += u;
        }
        warpsum[lane] = wi;
        unsigned total = (unsigned)__shfl_sync(0xffffffffu, wi, 31);
        if (b == 0) {
            if (lane == 0) {
                atomicExch(&state[0], (2ULL << 32) | total);
                s_base = 0;
            }
        } else {
            if (lane == 0) atomicExch(&state[b], (1ULL << 32) | total);
            unsigned running = 0;
            int idx = b - 1;
            while (true) {
                int ii = idx - lane;
                unsigned long long s64 = (ii >= 0)
                    ? atomicAdd(&state[ii], 0ULL) : (2ULL << 32);
                unsigned flag = (unsigned)(s64 >> 32);
                if (__all_sync(0xffffffffu, flag != 0)) {
                    unsigned pm = __ballot_sync(0xffffffffu, flag == 2u);
                    if (pm) {
                        int k = __ffs(pm) - 1;
                        unsigned c = (lane <= k) ? (unsigned)s64 : 0u;
#pragma unroll
                        for (int o = 16; o; o >>= 1)
                            c += __shfl_down_sync(0xffffffffu, c, o);
                        running += __shfl_sync(0xffffffffu, c, 0);
                        break;
                    } else {
                        unsigned c = (unsigned)s64;
#pragma unroll
                        for (int o = 16; o; o >>= 1)
                            c += __shfl_down_sync(0xffffffffu, c, o);
                        running += __shfl_sync(0xffffffffu, c, 0);
                        idx -= 32;
                    }
                }
            }
            if (lane == 0) {
                atomicExch(&state[b], (2ULL << 32) | (running + total));
                s_base = (int)running;
                if (b == NB - 1) off[N_NODES] = (int)(running + total);
            }
        }
    }
    __syncthreads();
    int base = s_base;
    int woff = (w > 0) ? warpsum[w - 1] : 0;
    if (i < N_NODES) {
        int e = base + woff + inc - v;
        off[i] = e;
        cursor[i] = e;
        dis[i] = rsqrtf((float)(v + 1));
    }
}

__global__ void k_fill(const int* __restrict__ row, const int* __restrict__ col,
                       const float* __restrict__ dis,
                       int* __restrict__ cursor, int2* __restrict__ edge) {
    int e = blockIdx.x * blockDim.x + threadIdx.x;
    if (e >= N_EDGES) return;
    int r = row[e], c = col[e];
    int pos = atomicAdd(&cursor[c], 1);
    edge[pos] = make_int2(r, __float_as_int(dis[r] * dis[c]));
}

// ---------------- layer-0 pre-aggregate: xagg = Â x (128 ch, 2-wide, f32x2) --
__global__ __launch_bounds__(256) void k_agg0(const __half* __restrict__ xh,
                                              const int* __restrict__ off,
                                              const int2* __restrict__ edge,
                                              const float* __restrict__ dis,
                                              __half* __restrict__ xagg) {
    int nid  = blockIdx.x * 8 + (threadIdx.x >> 5);
    int lane = threadIdx.x & 31;
    if (nid >= N_NODES) return;
    float d  = dis[nid];
    float d2 = d * d;
    uint2 sv = *(const uint2*)&xh[(size_t)nid * IN_CH + lane * 4];
    float2 s0 = __half22float2(*(const __half2*)&sv.x);
    float2 s1 = __half22float2(*(const __half2*)&sv.y);
    u64t a0 = packf2(s0.x * d2, s0.y * d2);
    u64t a1 = packf2(s1.x * d2, s1.y * d2);
    int s = off[nid], e = off[nid + 1];
    int j = s;
    for (; j + 1 < e; j += 2) {
        int2 e0 = __ldg(&edge[j]);
        int2 e1 = __ldg(&edge[j + 1]);
        float w0 = __int_as_float(e0.y), w1 = __int_as_float(e1.y);
        u64t wd0 = packf2(w0, w0), wd1 = packf2(w1, w1);
        uint2 v0 = *(const uint2*)&xh[(size_t)e0.x * IN_CH + lane * 4];
        uint2 v1 = *(const uint2*)&xh[(size_t)e1.x * IN_CH + lane * 4];
        float2 f00 = __half22float2(*(const __half2*)&v0.x);
        float2 f01 = __half22float2(*(const __half2*)&v0.y);
        float2 f10 = __half22float2(*(const __half2*)&v1.x);
        float2 f11 = __half22float2(*(const __half2*)&v1.y);
        FMA_F32X2(a0, packf2(f00.x, f00.y), wd0, a0);
        FMA_F32X2(a1, packf2(f01.x, f01.y), wd0, a1);
        FMA_F32X2(a0, packf2(f10.x, f10.y), wd1, a0);
        FMA_F32X2(a1, packf2(f11.x, f11.y), wd1, a1);
    }
    if (j < e) {
        int2 e0 = __ldg(&edge[j]);
        float w0 = __int_as_float(e0.y);
        u64t wd0 = packf2(w0, w0);
        uint2 v0 = *(const uint2*)&xh[(size_t)e0.x * IN_CH + lane * 4];
        float2 f00 = __half22float2(*(const __half2*)&v0.x);
        float2 f01 = __half22float2(*(const __half2*)&v0.y);
        FMA_F32X2(a0, packf2(f00.x, f00.y), wd0, a0);
        FMA_F32X2(a1, packf2(f01.x, f01.y), wd0, a1);
    }
    float2 r0 = unpackf2(a0), r1 = unpackf2(a1);
    uint2 o;
    *(__half2*)&o.x = __floats2half2_rn(r0.x, r0.y);
    *(__half2*)&o.y = __floats2half2_rn(r1.x, r1.y);
    *(uint2*)&xagg[(size_t)nid * IN_CH + lane * 4] = o;
}

// ---------------- FP16 tensor-core GEMM, cp.async 2-stage double buffer ------
#define BM 128
#define BN 128
#define BK 32
#define SSTR 72
#define STG_H (BM * SSTR)                 // halves per stage (A or B)
#define GEMM_SMEM (4 * STG_H * 2)         // bytes: 2 stages x (A+B)

template <bool BIASRELU>
__global__ __launch_bounds__(256) void k_hgemm(const __half* __restrict__ A,
                                               const __half* __restrict__ Bt,
                                               __half* __restrict__ C,
                                               const float* __restrict__ bias,
                                               int M, int K) {
    extern __shared__ __half sh[];
    __half* AsBase = sh;
    __half* BsBase = sh + 2 * STG_H;
    const int tid  = threadIdx.x;
    const int warp = tid >> 5, lane = tid & 31;
    const int wm = (warp & 3) * 32;
    const int wn = (warp >> 2) * 64;
    const int r = lane >> 2, c = lane & 3;
    const int bm = blockIdx.y * BM;
    const int bn = blockIdx.x * BN;

    const int arow0 = (tid) >> 2,        acg0 = ((tid) & 3) * 8;
    const int arow1 = (tid + 256) >> 2,  acg1 = ((tid + 256) & 3) * 8;
    const int gm0 = bm + arow0, gm1 = bm + arow1;
    const int pb0 = (gm0 < M) ? 16 : 0, pb1 = (gm1 < M) ? 16 : 0;

    uint32_t sA = (uint32_t)__cvta_generic_to_shared(AsBase);
    uint32_t sB = (uint32_t)__cvta_generic_to_shared(BsBase);
    const uint32_t oA0 = (arow0 * SSTR + acg0) * 2;
    const uint32_t oA1 = (arow1 * SSTR + acg1) * 2;

    float acc[2][8][4];
#pragma unroll
    for (int mt = 0; mt < 2; mt++)
#pragma unroll
        for (int nt = 0; nt < 8; nt++)
#pragma unroll
            for (int q = 0; q < 4; q++) acc[mt][nt][q] = 0.0f;

    const int tiles = K / BK;

    {
        cp16(sA + oA0, &A[(size_t)gm0 * K + acg0], pb0);
        cp16(sA + oA1, &A[(size_t)gm1 * K + acg1], pb1);
        cp16(sB + oA0, &Bt[(size_t)(bn + arow0) * K + acg0], 16);
        cp16(sB + oA1, &Bt[(size_t)(bn + arow1) * K + acg1], 16);
        asm volatile("cp.async.commit_group;");
    }

    for (int t = 0; t < tiles; t++) {
        const int stg = t & 1;
        if (t + 1 < tiles) {
            const int kn = (t + 1) * BK;
            const uint32_t so = (stg ^ 1) * STG_H * 2;
            cp16(sA + so + oA0, &A[(size_t)gm0 * K + kn + acg0], pb0);
            cp16(sA + so + oA1, &A[(size_t)gm1 * K + kn + acg1], pb1);
            cp16(sB + so + oA0, &Bt[(size_t)(bn + arow0) * K + kn + acg0], 16);
            cp16(sB + so + oA1, &Bt[(size_t)(bn + arow1) * K + kn + acg1], 16);
            asm volatile("cp.async.commit_group;");
            asm volatile("cp.async.wait_group 1;");
        } else {
            asm volatile("cp.async.wait_group 0;");
        }
        __syncthreads();
        const __half* As = AsBase + stg * STG_H;
        const __half* Bs = BsBase + stg * STG_H;
#pragma unroll
        for (int ks = 0; ks < 2; ks++) {
            const int kk = ks * 16;
            uint32_t a[2][4];
#pragma unroll
            for (int mt = 0; mt < 2; mt++) {
                int base = wm + mt * 16;
                a[mt][0] = *(const uint32_t*)&As[(base + r    ) * SSTR + kk + 2 * c];
                a[mt][1] = *(const uint32_t*)&As[(base + r + 8) * SSTR + kk + 2 * c];
                a[mt][2] = *(const uint32_t*)&As[(base + r    ) * SSTR + kk + 8 + 2 * c];
                a[mt][3] = *(const uint32_t*)&As[(base + r + 8) * SSTR + kk + 8 + 2 * c];
            }
#pragma unroll
            for (int nt = 0; nt < 8; nt++) {
                uint32_t b0 = *(const uint32_t*)&Bs[(wn + nt * 8 + r) * SSTR + kk + 2 * c];
                uint32_t b1 = *(const uint32_t*)&Bs[(wn + nt * 8 + r) * SSTR + kk + 8 + 2 * c];
#pragma unroll
                for (int mt = 0; mt < 2; mt++) {
                    asm volatile(
                        "mma.sync.aligned.m16n8k16.row.col.f32.f16.f16.f32 "
                        "{%0,%1,%2,%3}, {%4,%5,%6,%7}, {%8,%9}, {%0,%1,%2,%3};"
                        : "+f"(acc[mt][nt][0]), "+f"(acc[mt][nt][1]),
                          "+f"(acc[mt][nt][2]), "+f"(acc[mt][nt][3])
                        : "r"(a[mt][0]), "r"(a[mt][1]), "r"(a[mt][2]), "r"(a[mt][3]),
                          "r"(b0), "r"(b1));
                }
            }
        }
        __syncthreads();
    }
#pragma unroll
    for (int mt = 0; mt < 2; mt++) {
        int row0 = bm + wm + mt * 16 + r;
#pragma unroll
        for (int nt = 0; nt < 8; nt++) {
            int cc = bn + wn + nt * 8 + 2 * c;
            float v0 = acc[mt][nt][0], v1 = acc[mt][nt][1];
            float v2 = acc[mt][nt][2], v3 = acc[mt][nt][3];
            if (BIASRELU) {
                float2 bv = *(const float2*)&bias[cc];
                v0 = fmaxf(v0 + bv.x, 0.f); v1 = fmaxf(v1 + bv.y, 0.f);
                v2 = fmaxf(v2 + bv.x, 0.f); v3 = fmaxf(v3 + bv.y, 0.f);
            }
            if (row0 < M)
                *(__half2*)&C[(size_t)row0 * HID + cc] = __floats2half2_rn(v0, v1);
            if (row0 + 8 < M)
                *(__half2*)&C[(size_t)(row0 + 8) * HID + cc] = __floats2half2_rn(v2, v3);
        }
    }
}

// ---------------- full aggregate (256 ch, dual-chain HFMA2, 2-wide) ----------
template <bool POOL>
__global__ __launch_bounds__(256) void k_agg_h(const __half* __restrict__ xw,
                                               const int* __restrict__ off,
                                               const int2* __restrict__ edge,
                                               const float* __restrict__ dis,
                                               const float* __restrict__ bias,
                                               __half* __restrict__ out,
                                               const int* __restrict__ batch,
                                               float* __restrict__ pooled) {
    int nid  = blockIdx.x * 8 + (threadIdx.x >> 5);
    int lane = threadIdx.x & 31;
    if (nid >= N_NODES) return;
    __half2 c0[4], c1[4];
    const __half2 hz = __float2half2_rn(0.0f);
#pragma unroll
    for (int q = 0; q < 4; q++) { c0[q] = hz; c1[q] = hz; }
    int s = off[nid], e = off[nid + 1];
    int j = s;
    for (; j + 1 < e; j += 2) {
        int2 e0 = __ldg(&edge[j]);
        int2 e1 = __ldg(&edge[j + 1]);
        __half2 w0 = __float2half2_rn(__int_as_float(e0.y));
        __half2 w1 = __float2half2_rn(__int_as_float(e1.y));
        uint4 v0 = *(const uint4*)&xw[(size_t)e0.x * HID + lane * 8];
        uint4 v1 = *(const uint4*)&xw[(size_t)e1.x * HID + lane * 8];
        c0[0] = __hfma2(*(const __half2*)&v0.x, w0, c0[0]);
        c0[1] = __hfma2(*(const __half2*)&v0.y, w0, c0[1]);
        c0[2] = __hfma2(*(const __half2*)&v0.z, w0, c0[2]);
        c0[3] = __hfma2(*(const __half2*)&v0.w, w0, c0[3]);
        c1[0] = __hfma2(*(const __half2*)&v1.x, w1, c1[0]);
        c1[1] = __hfma2(*(const __half2*)&v1.y, w1, c1[1]);
        c1[2] = __hfma2(*(const __half2*)&v1.z, w1, c1[2]);
        c1[3] = __hfma2(*(const __half2*)&v1.w, w1, c1[3]);
    }
    if (j < e) {
        int2 e0 = __ldg(&edge[j]);
        __half2 w0 = __float2half2_rn(__int_as_float(e0.y));
        uint4 v0 = *(const uint4*)&xw[(size_t)e0.x * HID + lane * 8];
        c0[0] = __hfma2(*(const __half2*)&v0.x, w0, c0[0]);
        c0[1] = __hfma2(*(const __half2*)&v0.y, w0, c0[1]);
        c0[2] = __hfma2(*(const __half2*)&v0.z, w0, c0[2]);
        c0[3] = __hfma2(*(const __half2*)&v0.w, w0, c0[3]);
    }
    float d = dis[nid];
    float d2 = d * d;
    float f[8], acc[8];
    uint4 sv = *(const uint4*)&xw[(size_t)nid * HID + lane * 8];
    h8f(sv, f);
#pragma unroll
    for (int q = 0; q < 4; q++) {
        float2 fa = __half22float2(c0[q]);
        float2 fb = __half22float2(c1[q]);
        acc[2 * q]     = fa.x + fb.x;
        acc[2 * q + 1] = fa.y + fb.y;
    }
    float4 b0 = *(const float4*)&bias[lane * 8];
    float4 b1 = *(const float4*)&bias[lane * 8 + 4];
    acc[0] = fmaf(f[0], d2, acc[0]) + b0.x; acc[1] = fmaf(f[1], d2, acc[1]) + b0.y;
    acc[2] = fmaf(f[2], d2, acc[2]) + b0.z; acc[3] = fmaf(f[3], d2, acc[3]) + b0.w;
    acc[4] = fmaf(f[4], d2, acc[4]) + b1.x; acc[5] = fmaf(f[5], d2, acc[5]) + b1.y;
    acc[6] = fmaf(f[6], d2, acc[6]) + b1.z; acc[7] = fmaf(f[7], d2, acc[7]) + b1.w;
#pragma unroll
    for (int q = 0; q < 8; q++) acc[q] = fmaxf(acc[q], 0.0f);
    if (POOL) {
        int bg = batch[nid];
        red_add_v4(&pooled[(size_t)bg * HID + lane * 8],
                   make_float4(acc[0], acc[1], acc[2], acc[3]));
        red_add_v4(&pooled[(size_t)bg * HID + lane * 8 + 4],
                   make_float4(acc[4], acc[5], acc[6], acc[7]));
    } else {
        uint4 o;
        *(__half2*)&o.x = __floats2half2_rn(acc[0], acc[1]);
        *(__half2*)&o.y = __floats2half2_rn(acc[2], acc[3]);
        *(__half2*)&o.z = __floats2half2_rn(acc[4], acc[5]);
        *(__half2*)&o.w = __floats2half2_rn(acc[6], acc[7]);
        *(uint4*)&out[(size_t)nid * HID + lane * 8] = o;
    }
}

// ---------------- FFN --------------------------------------------------------
__global__ __launch_bounds__(256) void k_ffn(const float* __restrict__ pooled,
                                             const float* __restrict__ counts,
                                             const float* __restrict__ Wf,
                                             const float* __restrict__ bf,
                                             const float* __restrict__ Wo,
                                             const float* __restrict__ bo,
                                             float* __restrict__ out) {
    int g = blockIdx.x;
    int t = threadIdx.x;
    __shared__ float prow[HID];
    __shared__ float red[HID];
    float inv = 1.0f / fmaxf(counts[g], 1.0f);
    prow[t] = pooled[g * HID + t] * inv;
    __syncthreads();
    float acc = bf[t];
#pragma unroll 8
    for (int k = 0; k < HID; k++) acc = fmaf(prow[k], Wf[k * HID + t], acc);
    red[t] = fmaxf(acc, 0.0f) * Wo[t];
    __syncthreads();
    for (int s = 128; s > 0; s >>= 1) {
        if (t < s) red[t] += red[t + s];
        __syncthreads();
    }
    if (t == 0) out[g] = red[0] + bo[0];
}

// ---------------- host side ---------------------------------------------------
extern "C" void kernel_launch(void* const* d_in, const int* in_sizes, int n_in,
                              void* d_out, int out_size) {
    const float* x    = (const float*)d_in[0];
    const int*   ei   = (const int*)d_in[1];
    const int*   batch= (const int*)d_in[2];
    const float* W1   = (const float*)d_in[3];
    const float* b1   = (const float*)d_in[4];
    const float* W2   = (const float*)d_in[5];
    const float* b2   = (const float*)d_in[6];
    const float* W3   = (const float*)d_in[7];
    const float* b3   = (const float*)d_in[8];
    const float* Wf   = (const float*)d_in[9];
    const float* bf   = (const float*)d_in[10];
    const float* Wo   = (const float*)d_in[11];
    const float* bo   = (const float*)d_in[12];
    float* out = (float*)d_out;

    const int* row = ei;
    const int* col = ei + N_EDGES;

    int *ideg, *off, *cursor;
    unsigned long long* state;
    int2* edge;
    float *dis, *pooled, *counts;
    __half *xh, *xagg, *Wt, *xw, *hA, *hB;
    cudaGetSymbolAddress((void**)&ideg,   g_ideg);
    cudaGetSymbolAddress((void**)&off,    g_off);
    cudaGetSymbolAddress((void**)&cursor, g_cursor);
    cudaGetSymbolAddress((void**)&state,  g_state);
    cudaGetSymbolAddress((void**)&edge,   g_edge);
    cudaGetSymbolAddress((void**)&dis,    g_dis);
    cudaGetSymbolAddress((void**)&xh,     g_xh);
    cudaGetSymbolAddress((void**)&xagg,   g_xagg);
    cudaGetSymbolAddress((void**)&Wt,     g_Wt);
    cudaGetSymbolAddress((void**)&xw,     g_xw);
    cudaGetSymbolAddress((void**)&hA,     g_hA);
    cudaGetSymbolAddress((void**)&hB,     g_hB);
    cudaGetSymbolAddress((void**)&pooled, g_pooled);
    cudaGetSymbolAddress((void**)&counts, g_counts);

    __half* Wt1 = Wt;
    __half* Wt2 = Wt + IN_CH * HID;
    __half* Wt3 = Wt2 + HID * HID;

    cudaFuncSetAttribute(k_hgemm<true>,
                         cudaFuncAttributeMaxDynamicSharedMemorySize, GEMM_SMEM);
    cudaFuncSetAttribute(k_hgemm<false>,
                         cudaFuncAttributeMaxDynamicSharedMemorySize, GEMM_SMEM);

    // ---- CSR build + prep ----
    k_zero<<<(N_GRAPHS * HID + 255) / 256, 256>>>(ideg, pooled, counts, state);
    k_count<<<(N_EDGES + 255) / 256, 256>>>(col, ideg, batch, counts);
    k_scan_fused<<<NB, 1024>>>(ideg, off, cursor, dis, state);
    k_fill<<<(N_EDGES + 255) / 256, 256>>>(row, col, dis, cursor, edge);
    int prep_items = XF4 + W1E + 2 * W23E;
    k_prep<<<(prep_items + 255) / 256, 256>>>(x, xh, W1, W2, W3, Wt);

    dim3 gemm_grid(HID / BN, (N_NODES + BM - 1) / BM);
    int node_blocks = (N_NODES + 7) / 8;

    // ---- layer 1: pre-aggregate (128 ch) then GEMM with bias+relu ----
    k_agg0<<<node_blocks, 256>>>(xh, off, edge, dis, xagg);
    k_hgemm<true><<<gemm_grid, 256, GEMM_SMEM>>>(xagg, Wt1, hA, b1, N_NODES, IN_CH);
    // ---- layer 2 ----
    k_hgemm<false><<<gemm_grid, 256, GEMM_SMEM>>>(hA, Wt2, xw, nullptr, N_NODES, HID);
    k_agg_h<false><<<node_blocks, 256>>>(xw, off, edge, dis, b2, hB, batch, pooled);
    // ---- layer 3 (pool fused) ----
    k_hgemm<false><<<gemm_grid, 256, GEMM_SMEM>>>(hB, Wt3, xw, nullptr, N_NODES, HID);
    k_agg_h<true><<<node_blocks, 256>>>(xw, off, edge, dis, b3, nullptr, batch, pooled);

    // ---- FFN ----
    k_ffn<<<N_GRAPHS, HID>>>(pooled, counts, Wf, bf, Wo, bo, out);
}

// round 12
// speedup vs baseline: 1.3666x; 1.0014x over previous
#include <cuda_runtime.h>
#include <cuda_fp16.h>
#include <cstdint>

#define N_NODES 50000
#define N_EDGES 800000
#define N_GRAPHS 256
#define IN_CH 128
#define HID 256
#define NB 49   // scan blocks of 1024

// ---------------- scratch (device globals; no allocation allowed) -------------
__device__ int   g_ideg[N_NODES];
__device__ int   g_off[N_NODES + 1];
__device__ int   g_cursor[N_NODES];
__device__ unsigned long long g_state[NB];       // decoupled-lookback state
__device__ __align__(16) int2 g_edge[N_EDGES];   // {src, w-as-int}
__device__ float g_dis[N_NODES];
__device__ __align__(16) __half g_xh[(size_t)N_NODES * IN_CH];
__device__ __align__(16) __half g_xagg[(size_t)N_NODES * IN_CH];
__device__ __align__(16) __half g_Wt[(IN_CH + HID + HID) * HID];
__device__ __align__(16) __half g_xw[(size_t)N_NODES * HID];
__device__ __align__(16) __half g_hA[(size_t)N_NODES * HID];
__device__ __align__(16) __half g_hB[(size_t)N_NODES * HID];
__device__ float g_pooled[N_GRAPHS * HID];
__device__ float g_counts[N_GRAPHS];

// ---------------- helpers ----------------------------------------------------
__device__ __forceinline__ void red_add_v4(float* addr, float4 v) {
    asm volatile("red.global.add.v4.f32 [%0], {%1,%2,%3,%4};"
                 :: "l"(addr), "f"(v.x), "f"(v.y), "f"(v.z), "f"(v.w)
                 : "memory");
}

__device__ __forceinline__ void h8f(uint4 v, float* f) {
    float2 p0 = __half22float2(*(const __half2*)&v.x);
    float2 p1 = __half22float2(*(const __half2*)&v.y);
    float2 p2 = __half22float2(*(const __half2*)&v.z);
    float2 p3 = __half22float2(*(const __half2*)&v.w);
    f[0] = p0.x; f[1] = p0.y; f[2] = p1.x; f[3] = p1.y;
    f[4] = p2.x; f[5] = p2.y; f[6] = p3.x; f[7] = p3.y;
}

typedef unsigned long long u64t;
__device__ __forceinline__ u64t packf2(float x, float y) {
    u64t u; asm("mov.b64 %0, {%1,%2};" : "=l"(u) : "f"(x), "f"(y)); return u;
}
__device__ __forceinline__ float2 unpackf2(u64t u) {
    float2 f; asm("mov.b64 {%0,%1}, %2;" : "=f"(f.x), "=f"(f.y) : "l"(u)); return f;
}
#define FMA_F32X2(d, a, b, c) \
    asm("fma.rn.f32x2 %0, %1, %2, %3;" : "=l"(d) : "l"(a), "l"(b), "l"(c))

__device__ __forceinline__ void cp16(uint32_t saddr, const void* g, int pbytes) {
    asm volatile("cp.async.ca.shared.global [%0], [%1], 16, %2;"
                 :: "r"(saddr), "l"(g), "r"(pbytes));
}

// ---------------- k_init: zeroing + fp16 prep (ALL pure streaming) -----------
#define XF4   (N_NODES * IN_CH / 4)
#define W1E   (IN_CH * HID)
#define W23E  (HID * HID)
#define PREP_ITEMS (XF4 + W1E + 2 * W23E)
__global__ void k_init(int* __restrict__ ideg, float* __restrict__ pooled,
                       float* __restrict__ counts, unsigned long long* __restrict__ state,
                       const float* __restrict__ x, __half* __restrict__ xh,
                       const float* __restrict__ W1, const float* __restrict__ W2,
                       const float* __restrict__ W3, __half* __restrict__ Wt) {
    int i = blockIdx.x * blockDim.x + threadIdx.x;
    if (i < N_NODES) ideg[i] = 0;
    if (i < N_GRAPHS * HID) pooled[i] = 0.0f;
    if (i < N_GRAPHS) counts[i] = 0.0f;
    if (i < NB) state[i] = 0ULL;
    int p = i;
    if (p < XF4) {
        float4 v = ((const float4*)x)[p];
        ((__half2*)xh)[p * 2]     = __floats2half2_rn(v.x, v.y);
        ((__half2*)xh)[p * 2 + 1] = __floats2half2_rn(v.z, v.w);
        return;
    }
    p -= XF4;
    if (p < W1E) {
        int k = p >> 8, n = p & 255;
        Wt[(size_t)n * IN_CH + k] = __float2half(W1[p]);
        return;
    }
    p -= W1E;
    if (p < W23E) {
        int k = p >> 8, n = p & 255;
        Wt[W1E + (size_t)n * HID + k] = __float2half(W2[p]);
        return;
    }
    p -= W23E;
    if (p < W23E) {
        int k = p >> 8, n = p & 255;
        Wt[W1E + W23E + (size_t)n * HID + k] = __float2half(W3[p]);
    }
}

// ---------------- CSR build ---------------------------------------------------
__global__ void k_count(const int* __restrict__ col, int* __restrict__ ideg,
                        const int* __restrict__ batch, float* __restrict__ counts) {
    int e = blockIdx.x * blockDim.x + threadIdx.x;
    if (e < N_EDGES) atomicAdd(&ideg[col[e]], 1);
    if (e < N_NODES) atomicAdd(&counts[batch[e]], 1.0f);
}

// single-kernel exclusive scan with warp-parallel decoupled lookback.
__global__ __launch_bounds__(1024) void k_scan_fused(const int* __restrict__ ideg,
                                                     int* __restrict__ off,
                                                     int* __restrict__ cursor,
                                                     float* __restrict__ dis,
                                                     unsigned long long* __restrict__ state) {
    __shared__ int warpsum[32];
    __shared__ int s_base;
    const int b = blockIdx.x, t = threadIdx.x;
    const int lane = t & 31, w = t >> 5;
    int i = b * 1024 + t;
    int v = (i < N_NODES) ? ideg[i] : 0;
    int inc = v;
#pragma unroll
    for (int s = 1; s < 32; s <<= 1) {
        int u = __shfl_up_sync(0xffffffffu, inc, s);
        if (lane >= s) inc += u;
    }
    if (lane == 31) warpsum[w] = inc;
    __syncthreads();
    if (w == 0) {
        int wi = warpsum[lane];
#pragma unroll
        for (int s = 1; s < 32; s <<= 1) {
            int u = __shfl_up_sync(0xffffffffu, wi, s);
            if (lane >= s) wi += u;
        }
        warpsum[lane] = wi;
        unsigned total = (unsigned)__shfl_sync(0xffffffffu, wi, 31);
        if (b == 0) {
            if (lane == 0) {
                atomicExch(&state[0], (2ULL << 32) | total);
                s_base = 0;
            }
        } else {
            if (lane == 0) atomicExch(&state[b], (1ULL << 32) | total);
            unsigned running = 0;
            int idx = b - 1;
            while (true) {
                int ii = idx - lane;
                unsigned long long s64 = (ii >= 0)
                    ? atomicAdd(&state[ii], 0ULL) : (2ULL << 32);
                unsigned flag = (unsigned)(s64 >> 32);
                if (__all_sync(0xffffffffu, flag != 0)) {
                    unsigned pm = __ballot_sync(0xffffffffu, flag == 2u);
                    if (pm) {
                        int k = __ffs(pm) - 1;
                        unsigned c = (lane <= k) ? (unsigned)s64 : 0u;
#pragma unroll
                        for (int o = 16; o; o >>= 1)
                            c += __shfl_down_sync(0xffffffffu, c, o);
                        running += __shfl_sync(0xffffffffu, c, 0);
                        break;
                    } else {
                        unsigned c = (unsigned)s64;
#pragma unroll
                        for (int o = 16; o; o >>= 1)
                            c += __shfl_down_sync(0xffffffffu, c, o);
                        running += __shfl_sync(0xffffffffu, c, 0);
                        idx -= 32;
                    }
                }
            }
            if (lane == 0) {
                atomicExch(&state[b], (2ULL << 32) | (running + total));
                s_base = (int)running;
                if (b == NB - 1) off[N_NODES] = (int)(running + total);
            }
        }
    }
    __syncthreads();
    int base = s_base;
    int woff = (w > 0) ? warpsum[w - 1] : 0;
    if (i < N_NODES) {
        int e = base + woff + inc - v;
        off[i] = e;
        cursor[i] = e;
        dis[i] = rsqrtf((float)(v + 1));
    }
}

__global__ void k_fill(const int* __restrict__ row, const int* __restrict__ col,
                       const float* __restrict__ dis,
                       int* __restrict__ cursor, int2* __restrict__ edge) {
    int e = blockIdx.x * blockDim.x + threadIdx.x;
    if (e >= N_EDGES) return;
    int r = row[e], c = col[e];
    int pos = atomicAdd(&cursor[c], 1);
    edge[pos] = make_int2(r, __float_as_int(dis[r] * dis[c]));
}

// ---------------- layer-0 pre-aggregate: xagg = Â x (128 ch, 2-wide, f32x2) --
__global__ __launch_bounds__(256) void k_agg0(const __half* __restrict__ xh,
                                              const int* __restrict__ off,
                                              const int2* __restrict__ edge,
                                              const float* __restrict__ dis,
                                              __half* __restrict__ xagg) {
    int nid  = blockIdx.x * 8 + (threadIdx.x >> 5);
    int lane = threadIdx.x & 31;
    if (nid >= N_NODES) return;
    float d  = dis[nid];
    float d2 = d * d;
    uint2 sv = *(const uint2*)&xh[(size_t)nid * IN_CH + lane * 4];
    float2 s0 = __half22float2(*(const __half2*)&sv.x);
    float2 s1 = __half22float2(*(const __half2*)&sv.y);
    u64t a0 = packf2(s0.x * d2, s0.y * d2);
    u64t a1 = packf2(s1.x * d2, s1.y * d2);
    int s = off[nid], e = off[nid + 1];
    int j = s;
    for (; j + 1 < e; j += 2) {
        int2 e0 = __ldg(&edge[j]);
        int2 e1 = __ldg(&edge[j + 1]);
        float w0 = __int_as_float(e0.y), w1 = __int_as_float(e1.y);
        u64t wd0 = packf2(w0, w0), wd1 = packf2(w1, w1);
        uint2 v0 = *(const uint2*)&xh[(size_t)e0.x * IN_CH + lane * 4];
        uint2 v1 = *(const uint2*)&xh[(size_t)e1.x * IN_CH + lane * 4];
        float2 f00 = __half22float2(*(const __half2*)&v0.x);
        float2 f01 = __half22float2(*(const __half2*)&v0.y);
        float2 f10 = __half22float2(*(const __half2*)&v1.x);
        float2 f11 = __half22float2(*(const __half2*)&v1.y);
        FMA_F32X2(a0, packf2(f00.x, f00.y), wd0, a0);
        FMA_F32X2(a1, packf2(f01.x, f01.y), wd0, a1);
        FMA_F32X2(a0, packf2(f10.x, f10.y), wd1, a0);
        FMA_F32X2(a1, packf2(f11.x, f11.y), wd1, a1);
    }
    if (j < e) {
        int2 e0 = __ldg(&edge[j]);
        float w0 = __int_as_float(e0.y);
        u64t wd0 = packf2(w0, w0);
        uint2 v0 = *(const uint2*)&xh[(size_t)e0.x * IN_CH + lane * 4];
        float2 f00 = __half22float2(*(const __half2*)&v0.x);
        float2 f01 = __half22float2(*(const __half2*)&v0.y);
        FMA_F32X2(a0, packf2(f00.x, f00.y), wd0, a0);
        FMA_F32X2(a1, packf2(f01.x, f01.y), wd0, a1);
    }
    float2 r0 = unpackf2(a0), r1 = unpackf2(a1);
    uint2 o;
    *(__half2*)&o.x = __floats2half2_rn(r0.x, r0.y);
    *(__half2*)&o.y = __floats2half2_rn(r1.x, r1.y);
    *(uint2*)&xagg[(size_t)nid * IN_CH + lane * 4] = o;
}

// ---------------- FP16 tensor-core GEMM, cp.async 2-stage double buffer ------
#define BM 128
#define BN 128
#define BK 32
#define SSTR 72
#define STG_H (BM * SSTR)                 // halves per stage (A or B)
#define GEMM_SMEM (4 * STG_H * 2)         // bytes: 2 stages x (A+B)

template <bool BIASRELU>
__global__ __launch_bounds__(256) void k_hgemm(const __half* __restrict__ A,
                                               const __half* __restrict__ Bt,
                                               __half* __restrict__ C,
                                               const float* __restrict__ bias,
                                               int M, int K) {
    extern __shared__ __half sh[];
    __half* AsBase = sh;
    __half* BsBase = sh + 2 * STG_H;
    const int tid  = threadIdx.x;
    const int warp = tid >> 5, lane = tid & 31;
    const int wm = (warp & 3) * 32;
    const int wn = (warp >> 2) * 64;
    const int r = lane >> 2, c = lane & 3;
    const int bm = blockIdx.y * BM;
    const int bn = blockIdx.x * BN;

    const int arow0 = (tid) >> 2,        acg0 = ((tid) & 3) * 8;
    const int arow1 = (tid + 256) >> 2,  acg1 = ((tid + 256) & 3) * 8;
    const int gm0 = bm + arow0, gm1 = bm + arow1;
    const int pb0 = (gm0 < M) ? 16 : 0, pb1 = (gm1 < M) ? 16 : 0;

    uint32_t sA = (uint32_t)__cvta_generic_to_shared(AsBase);
    uint32_t sB = (uint32_t)__cvta_generic_to_shared(BsBase);
    const uint32_t oA0 = (arow0 * SSTR + acg0) * 2;
    const uint32_t oA1 = (arow1 * SSTR + acg1) * 2;

    float acc[2][8][4];
#pragma unroll
    for (int mt = 0; mt < 2; mt++)
#pragma unroll
        for (int nt = 0; nt < 8; nt++)
#pragma unroll
            for (int q = 0; q < 4; q++) acc[mt][nt][q] = 0.0f;

    const int tiles = K / BK;

    {
        cp16(sA + oA0, &A[(size_t)gm0 * K + acg0], pb0);
        cp16(sA + oA1, &A[(size_t)gm1 * K + acg1], pb1);
        cp16(sB + oA0, &Bt[(size_t)(bn + arow0) * K + acg0], 16);
        cp16(sB + oA1, &Bt[(size_t)(bn + arow1) * K + acg1], 16);
        asm volatile("cp.async.commit_group;");
    }

    for (int t = 0; t < tiles; t++) {
        const int stg = t & 1;
        if (t + 1 < tiles) {
            const int kn = (t + 1) * BK;
            const uint32_t so = (stg ^ 1) * STG_H * 2;
            cp16(sA + so + oA0, &A[(size_t)gm0 * K + kn + acg0], pb0);
            cp16(sA + so + oA1, &A[(size_t)gm1 * K + kn + acg1], pb1);
            cp16(sB + so + oA0, &Bt[(size_t)(bn + arow0) * K + kn + acg0], 16);
            cp16(sB + so + oA1, &Bt[(size_t)(bn + arow1) * K + kn + acg1], 16);
            asm volatile("cp.async.commit_group;");
            asm volatile("cp.async.wait_group 1;");
        } else {
            asm volatile("cp.async.wait_group 0;");
        }
        __syncthreads();
        const __half* As = AsBase + stg * STG_H;
        const __half* Bs = BsBase + stg * STG_H;
#pragma unroll
        for (int ks = 0; ks < 2; ks++) {
            const int kk = ks * 16;
            uint32_t a[2][4];
#pragma unroll
            for (int mt = 0; mt < 2; mt++) {
                int base = wm + mt * 16;
                a[mt][0] = *(const uint32_t*)&As[(base + r    ) * SSTR + kk + 2 * c];
                a[mt][1] = *(const uint32_t*)&As[(base + r + 8) * SSTR + kk + 2 * c];
                a[mt][2] = *(const uint32_t*)&As[(base + r    ) * SSTR + kk + 8 + 2 * c];
                a[mt][3] = *(const uint32_t*)&As[(base + r + 8) * SSTR + kk + 8 + 2 * c];
            }
#pragma unroll
            for (int nt = 0; nt < 8; nt++) {
                uint32_t b0 = *(const uint32_t*)&Bs[(wn + nt * 8 + r) * SSTR + kk + 2 * c];
                uint32_t b1 = *(const uint32_t*)&Bs[(wn + nt * 8 + r) * SSTR + kk + 8 + 2 * c];
#pragma unroll
                for (int mt = 0; mt < 2; mt++) {
                    asm volatile(
                        "mma.sync.aligned.m16n8k16.row.col.f32.f16.f16.f32 "
                        "{%0,%1,%2,%3}, {%4,%5,%6,%7}, {%8,%9}, {%0,%1,%2,%3};"
                        : "+f"(acc[mt][nt][0]), "+f"(acc[mt][nt][1]),
                          "+f"(acc[mt][nt][2]), "+f"(acc[mt][nt][3])
                        : "r"(a[mt][0]), "r"(a[mt][1]), "r"(a[mt][2]), "r"(a[mt][3]),
                          "r"(b0), "r"(b1));
                }
            }
        }
        __syncthreads();
    }
#pragma unroll
    for (int mt = 0; mt < 2; mt++) {
        int row0 = bm + wm + mt * 16 + r;
#pragma unroll
        for (int nt = 0; nt < 8; nt++) {
            int cc = bn + wn + nt * 8 + 2 * c;
            float v0 = acc[mt][nt][0], v1 = acc[mt][nt][1];
            float v2 = acc[mt][nt][2], v3 = acc[mt][nt][3];
            if (BIASRELU) {
                float2 bv = *(const float2*)&bias[cc];
                v0 = fmaxf(v0 + bv.x, 0.f); v1 = fmaxf(v1 + bv.y, 0.f);
                v2 = fmaxf(v2 + bv.x, 0.f); v3 = fmaxf(v3 + bv.y, 0.f);
            }
            if (row0 < M)
                *(__half2*)&C[(size_t)row0 * HID + cc] = __floats2half2_rn(v0, v1);
            if (row0 + 8 < M)
                *(__half2*)&C[(size_t)(row0 + 8) * HID + cc] = __floats2half2_rn(v2, v3);
        }
    }
}

// ---------------- full aggregate (256 ch, dual-chain HFMA2, 2-wide) ----------
template <bool POOL>
__global__ __launch_bounds__(256) void k_agg_h(const __half* __restrict__ xw,
                                               const int* __restrict__ off,
                                               const int2* __restrict__ edge,
                                               const float* __restrict__ dis,
                                               const float* __restrict__ bias,
                                               __half* __restrict__ out,
                                               const int* __restrict__ batch,
                                               float* __restrict__ pooled) {
    int nid  = blockIdx.x * 8 + (threadIdx.x >> 5);
    int lane = threadIdx.x & 31;
    if (nid >= N_NODES) return;
    // hoist self-row load so its latency overlaps the gather loop
    uint4 sv = *(const uint4*)&xw[(size_t)nid * HID + lane * 8];
    float d = dis[nid];
    __half2 c0[4], c1[4];
    const __half2 hz = __float2half2_rn(0.0f);
#pragma unroll
    for (int q = 0; q < 4; q++) { c0[q] = hz; c1[q] = hz; }
    int s = off[nid], e = off[nid + 1];
    int j = s;
    for (; j + 1 < e; j += 2) {
        int2 e0 = __ldg(&edge[j]);
        int2 e1 = __ldg(&edge[j + 1]);
        __half2 w0 = __float2half2_rn(__int_as_float(e0.y));
        __half2 w1 = __float2half2_rn(__int_as_float(e1.y));
        uint4 v0 = *(const uint4*)&xw[(size_t)e0.x * HID + lane * 8];
        uint4 v1 = *(const uint4*)&xw[(size_t)e1.x * HID + lane * 8];
        c0[0] = __hfma2(*(const __half2*)&v0.x, w0, c0[0]);
        c0[1] = __hfma2(*(const __half2*)&v0.y, w0, c0[1]);
        c0[2] = __hfma2(*(const __half2*)&v0.z, w0, c0[2]);
        c0[3] = __hfma2(*(const __half2*)&v0.w, w0, c0[3]);
        c1[0] = __hfma2(*(const __half2*)&v1.x, w1, c1[0]);
        c1[1] = __hfma2(*(const __half2*)&v1.y, w1, c1[1]);
        c1[2] = __hfma2(*(const __half2*)&v1.z, w1, c1[2]);
        c1[3] = __hfma2(*(const __half2*)&v1.w, w1, c1[3]);
    }
    if (j < e) {
        int2 e0 = __ldg(&edge[j]);
        __half2 w0 = __float2half2_rn(__int_as_float(e0.y));
        uint4 v0 = *(const uint4*)&xw[(size_t)e0.x * HID + lane * 8];
        c0[0] = __hfma2(*(const __half2*)&v0.x, w0, c0[0]);
        c0[1] = __hfma2(*(const __half2*)&v0.y, w0, c0[1]);
        c0[2] = __hfma2(*(const __half2*)&v0.z, w0, c0[2]);
        c0[3] = __hfma2(*(const __half2*)&v0.w, w0, c0[3]);
    }
    float d2 = d * d;
    float f[8], acc[8];
    h8f(sv, f);
#pragma unroll
    for (int q = 0; q < 4; q++) {
        float2 fa = __half22float2(c0[q]);
        float2 fb = __half22float2(c1[q]);
        acc[2 * q]     = fa.x + fb.x;
        acc[2 * q + 1] = fa.y + fb.y;
    }
    float4 b0 = *(const float4*)&bias[lane * 8];
    float4 b1 = *(const float4*)&bias[lane * 8 + 4];
    acc[0] = fmaf(f[0], d2, acc[0]) + b0.x; acc[1] = fmaf(f[1], d2, acc[1]) + b0.y;
    acc[2] = fmaf(f[2], d2, acc[2]) + b0.z; acc[3] = fmaf(f[3], d2, acc[3]) + b0.w;
    acc[4] = fmaf(f[4], d2, acc[4]) + b1.x; acc[5] = fmaf(f[5], d2, acc[5]) + b1.y;
    acc[6] = fmaf(f[6], d2, acc[6]) + b1.z; acc[7] = fmaf(f[7], d2, acc[7]) + b1.w;
#pragma unroll
    for (int q = 0; q < 8; q++) acc[q] = fmaxf(acc[q], 0.0f);
    if (POOL) {
        int bg = batch[nid];
        red_add_v4(&pooled[(size_t)bg * HID + lane * 8],
                   make_float4(acc[0], acc[1], acc[2], acc[3]));
        red_add_v4(&pooled[(size_t)bg * HID + lane * 8 + 4],
                   make_float4(acc[4], acc[5], acc[6], acc[7]));
    } else {
        uint4 o;
        *(__half2*)&o.x = __floats2half2_rn(acc[0], acc[1]);
        *(__half2*)&o.y = __floats2half2_rn(acc[2], acc[3]);
        *(__half2*)&o.z = __floats2half2_rn(acc[4], acc[5]);
        *(__half2*)&o.w = __floats2half2_rn(acc[6], acc[7]);
        *(uint4*)&out[(size_t)nid * HID + lane * 8] = o;
    }
}

// ---------------- FFN --------------------------------------------------------
__global__ __launch_bounds__(256) void k_ffn(const float* __restrict__ pooled,
                                             const float* __restrict__ counts,
                                             const float* __restrict__ Wf,
                                             const float* __restrict__ bf,
                                             const float* __restrict__ Wo,
                                             const float* __restrict__ bo,
                                             float* __restrict__ out) {
    int g = blockIdx.x;
    int t = threadIdx.x;
    __shared__ float prow[HID];
    __shared__ float red[HID];
    float inv = 1.0f / fmaxf(counts[g], 1.0f);
    prow[t] = pooled[g * HID + t] * inv;
    __syncthreads();
    float acc = bf[t];
#pragma unroll 8
    for (int k = 0; k < HID; k++) acc = fmaf(prow[k], Wf[k * HID + t], acc);
    red[t] = fmaxf(acc, 0.0f) * Wo[t];
    __syncthreads();
    for (int s = 128; s > 0; s >>= 1) {
        if (t < s) red[t] += red[t + s];
        __syncthreads();
    }
    if (t == 0) out[g] = red[0] + bo[0];
}

// ---------------- host side ---------------------------------------------------
extern "C" void kernel_launch(void* const* d_in, const int* in_sizes, int n_in,
                              void* d_out, int out_size) {
    const float* x    = (const float*)d_in[0];
    const int*   ei   = (const int*)d_in[1];
    const int*   batch= (const int*)d_in[2];
    const float* W1   = (const float*)d_in[3];
    const float* b1   = (const float*)d_in[4];
    const float* W2   = (const float*)d_in[5];
    const float* b2   = (const float*)d_in[6];
    const float* W3   = (const float*)d_in[7];
    const float* b3   = (const float*)d_in[8];
    const float* Wf   = (const float*)d_in[9];
    const float* bf   = (const float*)d_in[10];
    const float* Wo   = (const float*)d_in[11];
    const float* bo   = (const float*)d_in[12];
    float* out = (float*)d_out;

    const int* row = ei;
    const int* col = ei + N_EDGES;

    int *ideg, *off, *cursor;
    unsigned long long* state;
    int2* edge;
    float *dis, *pooled, *counts;
    __half *xh, *xagg, *Wt, *xw, *hA, *hB;
    cudaGetSymbolAddress((void**)&ideg,   g_ideg);
    cudaGetSymbolAddress((void**)&off,    g_off);
    cudaGetSymbolAddress((void**)&cursor, g_cursor);
    cudaGetSymbolAddress((void**)&state,  g_state);
    cudaGetSymbolAddress((void**)&edge,   g_edge);
    cudaGetSymbolAddress((void**)&dis,    g_dis);
    cudaGetSymbolAddress((void**)&xh,     g_xh);
    cudaGetSymbolAddress((void**)&xagg,   g_xagg);
    cudaGetSymbolAddress((void**)&Wt,     g_Wt);
    cudaGetSymbolAddress((void**)&xw,     g_xw);
    cudaGetSymbolAddress((void**)&hA,     g_hA);
    cudaGetSymbolAddress((void**)&hB,     g_hB);
    cudaGetSymbolAddress((void**)&pooled, g_pooled);
    cudaGetSymbolAddress((void**)&counts, g_counts);

    __half* Wt1 = Wt;
    __half* Wt2 = Wt + IN_CH * HID;
    __half* Wt3 = Wt2 + HID * HID;

    cudaFuncSetAttribute(k_hgemm<true>,
                         cudaFuncAttributeMaxDynamicSharedMemorySize, GEMM_SMEM);
    cudaFuncSetAttribute(k_hgemm<false>,
                         cudaFuncAttributeMaxDynamicSharedMemorySize, GEMM_SMEM);

    // ---- init (zero + prep, pure streaming) then CSR build ----
    k_init<<<(PREP_ITEMS + 255) / 256, 256>>>(ideg, pooled, counts, state,
                                              x, xh, W1, W2, W3, Wt);
    k_count<<<(N_EDGES + 255) / 256, 256>>>(col, ideg, batch, counts);
    k_scan_fused<<<NB, 1024>>>(ideg, off, cursor, dis, state);
    k_fill<<<(N_EDGES + 255) / 256, 256>>>(row, col, dis, cursor, edge);

    dim3 gemm_grid(HID / BN, (N_NODES + BM - 1) / BM);
    int node_blocks = (N_NODES + 7) / 8;

    // ---- layer 1: pre-aggregate (128 ch) then GEMM with bias+relu ----
    k_agg0<<<node_blocks, 256>>>(xh, off, edge, dis, xagg);
    k_hgemm<true><<<gemm_grid, 256, GEMM_SMEM>>>(xagg, Wt1, hA, b1, N_NODES, IN_CH);
    // ---- layer 2 ----
    k_hgemm<false><<<gemm_grid, 256, GEMM_SMEM>>>(hA, Wt2, xw, nullptr, N_NODES, HID);
    k_agg_h<false><<<node_blocks, 256>>>(xw, off, edge, dis, b2, hB, batch, pooled);
    // ---- layer 3 (pool fused) ----
    k_hgemm<false><<<gemm_grid, 256, GEMM_SMEM>>>(hB, Wt3, xw, nullptr, N_NODES, HID);
    k_agg_h<true><<<node_blocks, 256>>>(xw, off, edge, dis, b3, nullptr, batch, pooled);

    // ---- FFN ----
    k_ffn<<<N_GRAPHS, HID>>>(pooled, counts, Wf, bf, Wo, bo, out);
}

// round 13
// speedup vs baseline: 1.3856x; 1.0139x over previous
#include <cuda_runtime.h>
#include <cuda_fp16.h>
#include <cstdint>

#define N_NODES 50000
#define N_EDGES 800000
#define N_GRAPHS 256
#define IN_CH 128
#define HID 256
#define NB 49   // scan blocks of 1024

// ---------------- scratch (device globals; no allocation allowed) -------------
__device__ int   g_ideg[N_NODES];
__device__ int   g_off[N_NODES + 1];
__device__ int   g_cursor[N_NODES];
__device__ unsigned long long g_state[NB];       // decoupled-lookback state
__device__ __align__(16) int2 g_edge[N_EDGES];   // {src, w-as-int}
__device__ float g_dis[N_NODES];
__device__ __align__(16) __half g_xh[(size_t)N_NODES * IN_CH];
__device__ __align__(16) __half g_xagg[(size_t)N_NODES * IN_CH];
__device__ __align__(16) __half g_Wt[(IN_CH + HID + HID) * HID];
__device__ __align__(16) __half g_xw[(size_t)N_NODES * HID];
__device__ __align__(16) __half g_hA[(size_t)N_NODES * HID];
__device__ __align__(16) __half g_hB[(size_t)N_NODES * HID];
__device__ float g_pooled[N_GRAPHS * HID];
__device__ float g_counts[N_GRAPHS];

// ---------------- helpers ----------------------------------------------------
__device__ __forceinline__ void red_add_v4(float* addr, float4 v) {
    asm volatile("red.global.add.v4.f32 [%0], {%1,%2,%3,%4};"
                 :: "l"(addr), "f"(v.x), "f"(v.y), "f"(v.z), "f"(v.w)
                 : "memory");
}

__device__ __forceinline__ void h8f(uint4 v, float* f) {
    float2 p0 = __half22float2(*(const __half2*)&v.x);
    float2 p1 = __half22float2(*(const __half2*)&v.y);
    float2 p2 = __half22float2(*(const __half2*)&v.z);
    float2 p3 = __half22float2(*(const __half2*)&v.w);
    f[0] = p0.x; f[1] = p0.y; f[2] = p1.x; f[3] = p1.y;
    f[4] = p2.x; f[5] = p2.y; f[6] = p3.x; f[7] = p3.y;
}

typedef unsigned long long u64t;
__device__ __forceinline__ u64t packf2(float x, float y) {
    u64t u; asm("mov.b64 %0, {%1,%2};" : "=l"(u) : "f"(x), "f"(y)); return u;
}
__device__ __forceinline__ float2 unpackf2(u64t u) {
    float2 f; asm("mov.b64 {%0,%1}, %2;" : "=f"(f.x), "=f"(f.y) : "l"(u)); return f;
}
#define FMA_F32X2(d, a, b, c) \
    asm("fma.rn.f32x2 %0, %1, %2, %3;" : "=l"(d) : "l"(a), "l"(b), "l"(c))

__device__ __forceinline__ void cp16(uint32_t saddr, const void* g, int pbytes) {
    asm volatile("cp.async.ca.shared.global [%0], [%1], 16, %2;"
                 :: "r"(saddr), "l"(g), "r"(pbytes));
}

// ---------------- k_zero: small zeroing pass (precedes both chains) ----------
__global__ void k_zero(int* __restrict__ ideg, float* __restrict__ pooled,
                       float* __restrict__ counts,
                       unsigned long long* __restrict__ state) {
    int i = blockIdx.x * blockDim.x + threadIdx.x;
    if (i < N_NODES) ideg[i] = 0;
    if (i < N_GRAPHS * HID) pooled[i] = 0.0f;
    if (i < N_GRAPHS) counts[i] = 0.0f;
    if (i < NB) state[i] = 0ULL;
}

// ---------------- k_prep: fp16 conversions (pure streaming) ------------------
#define XF4   (N_NODES * IN_CH / 4)
#define W1E   (IN_CH * HID)
#define W23E  (HID * HID)
#define PREP_ITEMS (XF4 + W1E + 2 * W23E)
__global__ void k_prep(const float* __restrict__ x, __half* __restrict__ xh,
                       const float* __restrict__ W1, const float* __restrict__ W2,
                       const float* __restrict__ W3, __half* __restrict__ Wt) {
    int p = blockIdx.x * blockDim.x + threadIdx.x;
    if (p < XF4) {
        float4 v = ((const float4*)x)[p];
        ((__half2*)xh)[p * 2]     = __floats2half2_rn(v.x, v.y);
        ((__half2*)xh)[p * 2 + 1] = __floats2half2_rn(v.z, v.w);
        return;
    }
    p -= XF4;
    if (p < W1E) {
        int k = p >> 8, n = p & 255;
        Wt[(size_t)n * IN_CH + k] = __float2half(W1[p]);
        return;
    }
    p -= W1E;
    if (p < W23E) {
        int k = p >> 8, n = p & 255;
        Wt[W1E + (size_t)n * HID + k] = __float2half(W2[p]);
        return;
    }
    p -= W23E;
    if (p < W23E) {
        int k = p >> 8, n = p & 255;
        Wt[W1E + W23E + (size_t)n * HID + k] = __float2half(W3[p]);
    }
}

// ---------------- CSR build ---------------------------------------------------
__global__ void k_count(const int* __restrict__ col, int* __restrict__ ideg,
                        const int* __restrict__ batch, float* __restrict__ counts) {
    int e = blockIdx.x * blockDim.x + threadIdx.x;
    if (e < N_EDGES) atomicAdd(&ideg[col[e]], 1);
    if (e < N_NODES) atomicAdd(&counts[batch[e]], 1.0f);
}

// single-kernel exclusive scan with warp-parallel decoupled lookback.
__global__ __launch_bounds__(1024) void k_scan_fused(const int* __restrict__ ideg,
                                                     int* __restrict__ off,
                                                     int* __restrict__ cursor,
                                                     float* __restrict__ dis,
                                                     unsigned long long* __restrict__ state) {
    __shared__ int warpsum[32];
    __shared__ int s_base;
    const int b = blockIdx.x, t = threadIdx.x;
    const int lane = t & 31, w = t >> 5;
    int i = b * 1024 + t;
    int v = (i < N_NODES) ? ideg[i] : 0;
    int inc = v;
#pragma unroll
    for (int s = 1; s < 32; s <<= 1) {
        int u = __shfl_up_sync(0xffffffffu, inc, s);
        if (lane >= s) inc += u;
    }
    if (lane == 31) warpsum[w] = inc;
    __syncthreads();
    if (w == 0) {
        int wi = warpsum[lane];
#pragma unroll
        for (int s = 1; s < 32; s <<= 1) {
            int u = __shfl_up_sync(0xffffffffu, wi, s);
            if (lane >= s) wi += u;
        }
        warpsum[lane] = wi;
        unsigned total = (unsigned)__shfl_sync(0xffffffffu, wi, 31);
        if (b == 0) {
            if (lane == 0) {
                atomicExch(&state[0], (2ULL << 32) | total);
                s_base = 0;
            }
        } else {
            if (lane == 0) atomicExch(&state[b], (1ULL << 32) | total);
            unsigned running = 0;
            int idx = b - 1;
            while (true) {
                int ii = idx - lane;
                unsigned long long s64 = (ii >= 0)
                    ? atomicAdd(&state[ii], 0ULL) : (2ULL << 32);
                unsigned flag = (unsigned)(s64 >> 32);
                if (__all_sync(0xffffffffu, flag != 0)) {
                    unsigned pm = __ballot_sync(0xffffffffu, flag == 2u);
                    if (pm) {
                        int k = __ffs(pm) - 1;
                        unsigned c = (lane <= k) ? (unsigned)s64 : 0u;
#pragma unroll
                        for (int o = 16; o; o >>= 1)
                            c += __shfl_down_sync(0xffffffffu, c, o);
                        running += __shfl_sync(0xffffffffu, c, 0);
                        break;
                    } else {
                        unsigned c = (unsigned)s64;
#pragma unroll
                        for (int o = 16; o; o >>= 1)
                            c += __shfl_down_sync(0xffffffffu, c, o);
                        running += __shfl_sync(0xffffffffu, c, 0);
                        idx -= 32;
                    }
                }
            }
            if (lane == 0) {
                atomicExch(&state[b], (2ULL << 32) | (running + total));
                s_base = (int)running;
                if (b == NB - 1) off[N_NODES] = (int)(running + total);
            }
        }
    }
    __syncthreads();
    int base = s_base;
    int woff = (w > 0) ? warpsum[w - 1] : 0;
    if (i < N_NODES) {
        int e = base + woff + inc - v;
        off[i] = e;
        cursor[i] = e;
        dis[i] = rsqrtf((float)(v + 1));
    }
}

__global__ void k_fill(const int* __restrict__ row, const int* __restrict__ col,
                       const float* __restrict__ dis,
                       int* __restrict__ cursor, int2* __restrict__ edge) {
    int e = blockIdx.x * blockDim.x + threadIdx.x;
    if (e >= N_EDGES) return;
    int r = row[e], c = col[e];
    int pos = atomicAdd(&cursor[c], 1);
    edge[pos] = make_int2(r, __float_as_int(dis[r] * dis[c]));
}

// ---------------- layer-0 pre-aggregate: xagg = Â x (128 ch, 2-wide, f32x2) --
__global__ __launch_bounds__(256) void k_agg0(const __half* __restrict__ xh,
                                              const int* __restrict__ off,
                                              const int2* __restrict__ edge,
                                              const float* __restrict__ dis,
                                              __half* __restrict__ xagg) {
    int nid  = blockIdx.x * 8 + (threadIdx.x >> 5);
    int lane = threadIdx.x & 31;
    if (nid >= N_NODES) return;
    float d  = dis[nid];
    float d2 = d * d;
    uint2 sv = *(const uint2*)&xh[(size_t)nid * IN_CH + lane * 4];
    float2 s0 = __half22float2(*(const __half2*)&sv.x);
    float2 s1 = __half22float2(*(const __half2*)&sv.y);
    u64t a0 = packf2(s0.x * d2, s0.y * d2);
    u64t a1 = packf2(s1.x * d2, s1.y * d2);
    int s = off[nid], e = off[nid + 1];
    int j = s;
    for (; j + 1 < e; j += 2) {
        int2 e0 = __ldg(&edge[j]);
        int2 e1 = __ldg(&edge[j + 1]);
        float w0 = __int_as_float(e0.y), w1 = __int_as_float(e1.y);
        u64t wd0 = packf2(w0, w0), wd1 = packf2(w1, w1);
        uint2 v0 = *(const uint2*)&xh[(size_t)e0.x * IN_CH + lane * 4];
        uint2 v1 = *(const uint2*)&xh[(size_t)e1.x * IN_CH + lane * 4];
        float2 f00 = __half22float2(*(const __half2*)&v0.x);
        float2 f01 = __half22float2(*(const __half2*)&v0.y);
        float2 f10 = __half22float2(*(const __half2*)&v1.x);
        float2 f11 = __half22float2(*(const __half2*)&v1.y);
        FMA_F32X2(a0, packf2(f00.x, f00.y), wd0, a0);
        FMA_F32X2(a1, packf2(f01.x, f01.y), wd0, a1);
        FMA_F32X2(a0, packf2(f10.x, f10.y), wd1, a0);
        FMA_F32X2(a1, packf2(f11.x, f11.y), wd1, a1);
    }
    if (j < e) {
        int2 e0 = __ldg(&edge[j]);
        float w0 = __int_as_float(e0.y);
        u64t wd0 = packf2(w0, w0);
        uint2 v0 = *(const uint2*)&xh[(size_t)e0.x * IN_CH + lane * 4];
        float2 f00 = __half22float2(*(const __half2*)&v0.x);
        float2 f01 = __half22float2(*(const __half2*)&v0.y);
        FMA_F32X2(a0, packf2(f00.x, f00.y), wd0, a0);
        FMA_F32X2(a1, packf2(f01.x, f01.y), wd0, a1);
    }
    float2 r0 = unpackf2(a0), r1 = unpackf2(a1);
    uint2 o;
    *(__half2*)&o.x = __floats2half2_rn(r0.x, r0.y);
    *(__half2*)&o.y = __floats2half2_rn(r1.x, r1.y);
    *(uint2*)&xagg[(size_t)nid * IN_CH + lane * 4] = o;
}

// ---------------- FP16 tensor-core GEMM, cp.async 2-stage double buffer ------
#define BM 128
#define BN 128
#define BK 32
#define SSTR 72
#define STG_H (BM * SSTR)                 // halves per stage (A or B)
#define GEMM_SMEM (4 * STG_H * 2)         // bytes: 2 stages x (A+B)

template <bool BIASRELU>
__global__ __launch_bounds__(256) void k_hgemm(const __half* __restrict__ A,
                                               const __half* __restrict__ Bt,
                                               __half* __restrict__ C,
                                               const float* __restrict__ bias,
                                               int M, int K) {
    extern __shared__ __half sh[];
    __half* AsBase = sh;
    __half* BsBase = sh + 2 * STG_H;
    const int tid  = threadIdx.x;
    const int warp = tid >> 5, lane = tid & 31;
    const int wm = (warp & 3) * 32;
    const int wn = (warp >> 2) * 64;
    const int r = lane >> 2, c = lane & 3;
    const int bm = blockIdx.y * BM;
    const int bn = blockIdx.x * BN;

    const int arow0 = (tid) >> 2,        acg0 = ((tid) & 3) * 8;
    const int arow1 = (tid + 256) >> 2,  acg1 = ((tid + 256) & 3) * 8;
    const int gm0 = bm + arow0, gm1 = bm + arow1;
    const int pb0 = (gm0 < M) ? 16 : 0, pb1 = (gm1 < M) ? 16 : 0;

    uint32_t sA = (uint32_t)__cvta_generic_to_shared(AsBase);
    uint32_t sB = (uint32_t)__cvta_generic_to_shared(BsBase);
    const uint32_t oA0 = (arow0 * SSTR + acg0) * 2;
    const uint32_t oA1 = (arow1 * SSTR + acg1) * 2;

    float acc[2][8][4];
#pragma unroll
    for (int mt = 0; mt < 2; mt++)
#pragma unroll
        for (int nt = 0; nt < 8; nt++)
#pragma unroll
            for (int q = 0; q < 4; q++) acc[mt][nt][q] = 0.0f;

    const int tiles = K / BK;

    {
        cp16(sA + oA0, &A[(size_t)gm0 * K + acg0], pb0);
        cp16(sA + oA1, &A[(size_t)gm1 * K + acg1], pb1);
        cp16(sB + oA0, &Bt[(size_t)(bn + arow0) * K + acg0], 16);
        cp16(sB + oA1, &Bt[(size_t)(bn + arow1) * K + acg1], 16);
        asm volatile("cp.async.commit_group;");
    }

    for (int t = 0; t < tiles; t++) {
        const int stg = t & 1;
        if (t + 1 < tiles) {
            const int kn = (t + 1) * BK;
            const uint32_t so = (stg ^ 1) * STG_H * 2;
            cp16(sA + so + oA0, &A[(size_t)gm0 * K + kn + acg0], pb0);
            cp16(sA + so + oA1, &A[(size_t)gm1 * K + kn + acg1], pb1);
            cp16(sB + so + oA0, &Bt[(size_t)(bn + arow0) * K + kn + acg0], 16);
            cp16(sB + so + oA1, &Bt[(size_t)(bn + arow1) * K + kn + acg1], 16);
            asm volatile("cp.async.commit_group;");
            asm volatile("cp.async.wait_group 1;");
        } else {
            asm volatile("cp.async.wait_group 0;");
        }
        __syncthreads();
        const __half* As = AsBase + stg * STG_H;
        const __half* Bs = BsBase + stg * STG_H;
#pragma unroll
        for (int ks = 0; ks < 2; ks++) {
            const int kk = ks * 16;
            uint32_t a[2][4];
#pragma unroll
            for (int mt = 0; mt < 2; mt++) {
                int base = wm + mt * 16;
                a[mt][0] = *(const uint32_t*)&As[(base + r    ) * SSTR + kk + 2 * c];
                a[mt][1] = *(const uint32_t*)&As[(base + r + 8) * SSTR + kk + 2 * c];
                a[mt][2] = *(const uint32_t*)&As[(base + r    ) * SSTR + kk + 8 + 2 * c];
                a[mt][3] = *(const uint32_t*)&As[(base + r + 8) * SSTR + kk + 8 + 2 * c];
            }
#pragma unroll
            for (int nt = 0; nt < 8; nt++) {
                uint32_t b0 = *(const uint32_t*)&Bs[(wn + nt * 8 + r) * SSTR + kk + 2 * c];
                uint32_t b1 = *(const uint32_t*)&Bs[(wn + nt * 8 + r) * SSTR + kk + 8 + 2 * c];
#pragma unroll
                for (int mt = 0; mt < 2; mt++) {
                    asm volatile(
                        "mma.sync.aligned.m16n8k16.row.col.f32.f16.f16.f32 "
                        "{%0,%1,%2,%3}, {%4,%5,%6,%7}, {%8,%9}, {%0,%1,%2,%3};"
                        : "+f"(acc[mt][nt][0]), "+f"(acc[mt][nt][1]),
                          "+f"(acc[mt][nt][2]), "+f"(acc[mt][nt][3])
                        : "r"(a[mt][0]), "r"(a[mt][1]), "r"(a[mt][2]), "r"(a[mt][3]),
                          "r"(b0), "r"(b1));
                }
            }
        }
        __syncthreads();
    }
#pragma unroll
    for (int mt = 0; mt < 2; mt++) {
        int row0 = bm + wm + mt * 16 + r;
#pragma unroll
        for (int nt = 0; nt < 8; nt++) {
            int cc = bn + wn + nt * 8 + 2 * c;
            float v0 = acc[mt][nt][0], v1 = acc[mt][nt][1];
            float v2 = acc[mt][nt][2], v3 = acc[mt][nt][3];
            if (BIASRELU) {
                float2 bv = *(const float2*)&bias[cc];
                v0 = fmaxf(v0 + bv.x, 0.f); v1 = fmaxf(v1 + bv.y, 0.f);
                v2 = fmaxf(v2 + bv.x, 0.f); v3 = fmaxf(v3 + bv.y, 0.f);
            }
            if (row0 < M)
                *(__half2*)&C[(size_t)row0 * HID + cc] = __floats2half2_rn(v0, v1);
            if (row0 + 8 < M)
                *(__half2*)&C[(size_t)(row0 + 8) * HID + cc] = __floats2half2_rn(v2, v3);
        }
    }
}

// ---------------- full aggregate (256 ch, dual-chain HFMA2, 2-wide) ----------
template <bool POOL>
__global__ __launch_bounds__(256) void k_agg_h(const __half* __restrict__ xw,
                                               const int* __restrict__ off,
                                               const int2* __restrict__ edge,
                                               const float* __restrict__ dis,
                                               const float* __restrict__ bias,
                                               __half* __restrict__ out,
                                               const int* __restrict__ batch,
                                               float* __restrict__ pooled) {
    int nid  = blockIdx.x * 8 + (threadIdx.x >> 5);
    int lane = threadIdx.x & 31;
    if (nid >= N_NODES) return;
    uint4 sv = *(const uint4*)&xw[(size_t)nid * HID + lane * 8];
    float d = dis[nid];
    __half2 c0[4], c1[4];
    const __half2 hz = __float2half2_rn(0.0f);
#pragma unroll
    for (int q = 0; q < 4; q++) { c0[q] = hz; c1[q] = hz; }
    int s = off[nid], e = off[nid + 1];
    int j = s;
    for (; j + 1 < e; j += 2) {
        int2 e0 = __ldg(&edge[j]);
        int2 e1 = __ldg(&edge[j + 1]);
        __half2 w0 = __float2half2_rn(__int_as_float(e0.y));
        __half2 w1 = __float2half2_rn(__int_as_float(e1.y));
        uint4 v0 = *(const uint4*)&xw[(size_t)e0.x * HID + lane * 8];
        uint4 v1 = *(const uint4*)&xw[(size_t)e1.x * HID + lane * 8];
        c0[0] = __hfma2(*(const __half2*)&v0.x, w0, c0[0]);
        c0[1] = __hfma2(*(const __half2*)&v0.y, w0, c0[1]);
        c0[2] = __hfma2(*(const __half2*)&v0.z, w0, c0[2]);
        c0[3] = __hfma2(*(const __half2*)&v0.w, w0, c0[3]);
        c1[0] = __hfma2(*(const __half2*)&v1.x, w1, c1[0]);
        c1[1] = __hfma2(*(const __half2*)&v1.y, w1, c1[1]);
        c1[2] = __hfma2(*(const __half2*)&v1.z, w1, c1[2]);
        c1[3] = __hfma2(*(const __half2*)&v1.w, w1, c1[3]);
    }
    if (j < e) {
        int2 e0 = __ldg(&edge[j]);
        __half2 w0 = __float2half2_rn(__int_as_float(e0.y));
        uint4 v0 = *(const uint4*)&xw[(size_t)e0.x * HID + lane * 8];
        c0[0] = __hfma2(*(const __half2*)&v0.x, w0, c0[0]);
        c0[1] = __hfma2(*(const __half2*)&v0.y, w0, c0[1]);
        c0[2] = __hfma2(*(const __half2*)&v0.z, w0, c0[2]);
        c0[3] = __hfma2(*(const __half2*)&v0.w, w0, c0[3]);
    }
    float d2 = d * d;
    float f[8], acc[8];
    h8f(sv, f);
#pragma unroll
    for (int q = 0; q < 4; q++) {
        float2 fa = __half22float2(c0[q]);
        float2 fb = __half22float2(c1[q]);
        acc[2 * q]     = fa.x + fb.x;
        acc[2 * q + 1] = fa.y + fb.y;
    }
    float4 b0 = *(const float4*)&bias[lane * 8];
    float4 b1 = *(const float4*)&bias[lane * 8 + 4];
    acc[0] = fmaf(f[0], d2, acc[0]) + b0.x; acc[1] = fmaf(f[1], d2, acc[1]) + b0.y;
    acc[2] = fmaf(f[2], d2, acc[2]) + b0.z; acc[3] = fmaf(f[3], d2, acc[3]) + b0.w;
    acc[4] = fmaf(f[4], d2, acc[4]) + b1.x; acc[5] = fmaf(f[5], d2, acc[5]) + b1.y;
    acc[6] = fmaf(f[6], d2, acc[6]) + b1.z; acc[7] = fmaf(f[7], d2, acc[7]) + b1.w;
#pragma unroll
    for (int q = 0; q < 8; q++) acc[q] = fmaxf(acc[q], 0.0f);
    if (POOL) {
        int bg = batch[nid];
        red_add_v4(&pooled[(size_t)bg * HID + lane * 8],
                   make_float4(acc[0], acc[1], acc[2], acc[3]));
        red_add_v4(&pooled[(size_t)bg * HID + lane * 8 + 4],
                   make_float4(acc[4], acc[5], acc[6], acc[7]));
    } else {
        uint4 o;
        *(__half2*)&o.x = __floats2half2_rn(acc[0], acc[1]);
        *(__half2*)&o.y = __floats2half2_rn(acc[2], acc[3]);
        *(__half2*)&o.z = __floats2half2_rn(acc[4], acc[5]);
        *(__half2*)&o.w = __floats2half2_rn(acc[6], acc[7]);
        *(uint4*)&out[(size_t)nid * HID + lane * 8] = o;
    }
}

// ---------------- FFN --------------------------------------------------------
__global__ __launch_bounds__(256) void k_ffn(const float* __restrict__ pooled,
                                             const float* __restrict__ counts,
                                             const float* __restrict__ Wf,
                                             const float* __restrict__ bf,
                                             const float* __restrict__ Wo,
                                             const float* __restrict__ bo,
                                             float* __restrict__ out) {
    int g = blockIdx.x;
    int t = threadIdx.x;
    __shared__ float prow[HID];
    __shared__ float red[HID];
    float inv = 1.0f / fmaxf(counts[g], 1.0f);
    prow[t] = pooled[g * HID + t] * inv;
    __syncthreads();
    float acc = bf[t];
#pragma unroll 8
    for (int k = 0; k < HID; k++) acc = fmaf(prow[k], Wf[k * HID + t], acc);
    red[t] = fmaxf(acc, 0.0f) * Wo[t];
    __syncthreads();
    for (int s = 128; s > 0; s >>= 1) {
        if (t < s) red[t] += red[t + s];
        __syncthreads();
    }
    if (t == 0) out[g] = red[0] + bo[0];
}

// ---------------- host side ---------------------------------------------------
extern "C" void kernel_launch(void* const* d_in, const int* in_sizes, int n_in,
                              void* d_out, int out_size) {
    const float* x    = (const float*)d_in[0];
    const int*   ei   = (const int*)d_in[1];
    const int*   batch= (const int*)d_in[2];
    const float* W1   = (const float*)d_in[3];
    const float* b1   = (const float*)d_in[4];
    const float* W2   = (const float*)d_in[5];
    const float* b2   = (const float*)d_in[6];
    const float* W3   = (const float*)d_in[7];
    const float* b3   = (const float*)d_in[8];
    const float* Wf   = (const float*)d_in[9];
    const float* bf   = (const float*)d_in[10];
    const float* Wo   = (const float*)d_in[11];
    const float* bo   = (const float*)d_in[12];
    float* out = (float*)d_out;

    const int* row = ei;
    const int* col = ei + N_EDGES;

    int *ideg, *off, *cursor;
    unsigned long long* state;
    int2* edge;
    float *dis, *pooled, *counts;
    __half *xh, *xagg, *Wt, *xw, *hA, *hB;
    cudaGetSymbolAddress((void**)&ideg,   g_ideg);
    cudaGetSymbolAddress((void**)&off,    g_off);
    cudaGetSymbolAddress((void**)&cursor, g_cursor);
    cudaGetSymbolAddress((void**)&state,  g_state);
    cudaGetSymbolAddress((void**)&edge,   g_edge);
    cudaGetSymbolAddress((void**)&dis,    g_dis);
    cudaGetSymbolAddress((void**)&xh,     g_xh);
    cudaGetSymbolAddress((void**)&xagg,   g_xagg);
    cudaGetSymbolAddress((void**)&Wt,     g_Wt);
    cudaGetSymbolAddress((void**)&xw,     g_xw);
    cudaGetSymbolAddress((void**)&hA,     g_hA);
    cudaGetSymbolAddress((void**)&hB,     g_hB);
    cudaGetSymbolAddress((void**)&pooled, g_pooled);
    cudaGetSymbolAddress((void**)&counts, g_counts);

    __half* Wt1 = Wt;
    __half* Wt2 = Wt + IN_CH * HID;
    __half* Wt3 = Wt2 + HID * HID;

    cudaFuncSetAttribute(k_hgemm<true>,
                         cudaFuncAttributeMaxDynamicSharedMemorySize, GEMM_SMEM);
    cudaFuncSetAttribute(k_hgemm<false>,
                         cudaFuncAttributeMaxDynamicSharedMemorySize, GEMM_SMEM);

    // one-time host-side resources (no device memory involved)
    static cudaStream_t s2 = nullptr;
    static cudaEvent_t evFork = nullptr, evJoin = nullptr;
    if (s2 == nullptr) {
        cudaStreamCreateWithFlags(&s2, cudaStreamNonBlocking);
        cudaEventCreateWithFlags(&evFork, cudaEventDisableTiming);
        cudaEventCreateWithFlags(&evJoin, cudaEventDisableTiming);
    }

    // ---- zero (both chains depend on it) ----
    k_zero<<<(N_GRAPHS * HID + 255) / 256, 256>>>(ideg, pooled, counts, state);

    // ---- fork: CSR chain on s2, prep on main stream ----
    cudaEventRecord(evFork, 0);
    cudaStreamWaitEvent(s2, evFork, 0);
    k_count<<<(N_EDGES + 255) / 256, 256, 0, s2>>>(col, ideg, batch, counts);
    k_scan_fused<<<NB, 1024, 0, s2>>>(ideg, off, cursor, dis, state);
    k_fill<<<(N_EDGES + 255) / 256, 256, 0, s2>>>(row, col, dis, cursor, edge);
    cudaEventRecord(evJoin, s2);

    k_prep<<<(PREP_ITEMS + 255) / 256, 256>>>(x, xh, W1, W2, W3, Wt);

    // ---- join: agg0 needs xh (main) + edges/dis (s2) ----
    cudaStreamWaitEvent(0, evJoin, 0);

    dim3 gemm_grid(HID / BN, (N_NODES + BM - 1) / BM);
    int node_blocks = (N_NODES + 7) / 8;

    // ---- layer 1: pre-aggregate (128 ch) then GEMM with bias+relu ----
    k_agg0<<<node_blocks, 256>>>(xh, off, edge, dis, xagg);
    k_hgemm<true><<<gemm_grid, 256, GEMM_SMEM>>>(xagg, Wt1, hA, b1, N_NODES, IN_CH);
    // ---- layer 2 ----
    k_hgemm<false><<<gemm_grid, 256, GEMM_SMEM>>>(hA, Wt2, xw, nullptr, N_NODES, HID);
    k_agg_h<false><<<node_blocks, 256>>>(xw, off, edge, dis, b2, hB, batch, pooled);
    // ---- layer 3 (pool fused) ----
    k_hgemm<false><<<gemm_grid, 256, GEMM_SMEM>>>(hB, Wt3, xw, nullptr, N_NODES, HID);
    k_agg_h<true><<<node_blocks, 256>>>(xw, off, edge, dis, b3, nullptr, batch, pooled);

    // ---- FFN ----
    k_ffn<<<N_GRAPHS, HID>>>(pooled, counts, Wf, bf, Wo, bo, out);
}